// round 1
// baseline (speedup 1.0000x reference)
#include <cuda_runtime.h>

#define B_   4
#define S_   2048
#define DIN  1024
#define DOUT 1024
#define H_   16
#define HD_  64

// Scratch (module-scope device arrays: allowed; no runtime allocation)
__device__ float g_Q[B_ * H_ * S_ * HD_];    // (b,h,s,hd)
__device__ float g_K[B_ * H_ * S_ * HD_];
__device__ float g_V[B_ * H_ * S_ * HD_];
__device__ float g_ctx[B_ * S_ * DOUT];      // (b,s,d)

// ---------------------------------------------------------------------------
// Kernel 1: fused QKV projection.  Y = X @ W{q,k,v}, written to (b,h,s,hd).
// BM=128, BN=128, BK=16, 256 threads, 8x8 per thread.
// grid = (M/128 = 64, 3*DOUT/128 = 24)
// ---------------------------------------------------------------------------
__global__ __launch_bounds__(256) void qkv_kernel(
    const float* __restrict__ x,
    const float* __restrict__ Wq,
    const float* __restrict__ Wk,
    const float* __restrict__ Wv)
{
    __shared__ float As[16][128];
    __shared__ float Bs[16][128];

    const int tid = threadIdx.x;
    const int ty  = tid >> 4;       // 0..15  (M direction, 8 rows each)
    const int tx  = tid & 15;       // 0..15  (N direction, 8 cols each)

    const int rowBase = blockIdx.x * 128;
    const int yb      = blockIdx.y;           // 0..23
    const int w       = yb >> 3;               // 0,1,2 -> Wq,Wk,Wv
    const int nInW    = (yb & 7) * 128;        // column offset within W

    const float* Wm = (w == 0) ? Wq : (w == 1) ? Wk : Wv;

    float acc[8][8];
    #pragma unroll
    for (int i = 0; i < 8; ++i)
        #pragma unroll
        for (int j = 0; j < 8; ++j) acc[i][j] = 0.0f;

    for (int kb = 0; kb < DIN; kb += 16) {
        // Load A tile (128 x 16), store transposed As[k][m]
        #pragma unroll
        for (int i = 0; i < 2; ++i) {
            int f  = tid + i * 256;          // 0..511
            int m  = f >> 2;                 // 0..127
            int kq = f & 3;                  // float4 index along k
            float4 v = *reinterpret_cast<const float4*>(
                &x[(size_t)(rowBase + m) * DIN + kb + kq * 4]);
            As[kq * 4 + 0][m] = v.x;
            As[kq * 4 + 1][m] = v.y;
            As[kq * 4 + 2][m] = v.z;
            As[kq * 4 + 3][m] = v.w;
        }
        // Load B tile (16 x 128): Bs[k][n] = W[kb+k][nInW+n]
        #pragma unroll
        for (int i = 0; i < 2; ++i) {
            int f  = tid + i * 256;          // 0..511
            int k  = f >> 5;                 // 0..15
            int nq = f & 31;                 // 0..31 float4 along n
            *reinterpret_cast<float4*>(&Bs[k][nq * 4]) =
                *reinterpret_cast<const float4*>(
                    &Wm[(size_t)(kb + k) * DOUT + nInW + nq * 4]);
        }
        __syncthreads();

        #pragma unroll
        for (int kk = 0; kk < 16; ++kk) {
            float4 a0 = *reinterpret_cast<const float4*>(&As[kk][ty * 8]);
            float4 a1 = *reinterpret_cast<const float4*>(&As[kk][ty * 8 + 4]);
            float4 b0 = *reinterpret_cast<const float4*>(&Bs[kk][tx * 8]);
            float4 b1 = *reinterpret_cast<const float4*>(&Bs[kk][tx * 8 + 4]);
            float a[8] = {a0.x, a0.y, a0.z, a0.w, a1.x, a1.y, a1.z, a1.w};
            float b[8] = {b0.x, b0.y, b0.z, b0.w, b1.x, b1.y, b1.z, b1.w};
            #pragma unroll
            for (int i = 0; i < 8; ++i)
                #pragma unroll
                for (int j = 0; j < 8; ++j)
                    acc[i][j] += a[i] * b[j];
        }
        __syncthreads();
    }

    // Epilogue: scatter into (b, h, s, hd) layout
    float* obuf = (w == 0) ? g_Q : (w == 1) ? g_K : g_V;
    const int h0     = (nInW >> 6) + (tx >> 3);   // head index for this thread
    const int hdBase = (tx & 7) * 8;              // hd offset (0..56)
    #pragma unroll
    for (int i = 0; i < 8; ++i) {
        int r  = rowBase + ty * 8 + i;
        int b  = r >> 11;
        int sr = r & 2047;
        float* o = &obuf[(((size_t)(b * H_ + h0) * S_ + sr) * HD_) + hdBase];
        float4 v0 = {acc[i][0], acc[i][1], acc[i][2], acc[i][3]};
        float4 v1 = {acc[i][4], acc[i][5], acc[i][6], acc[i][7]};
        *reinterpret_cast<float4*>(o)     = v0;
        *reinterpret_cast<float4*>(o + 4) = v1;
    }
}

// ---------------------------------------------------------------------------
// Kernel 2: causal flash attention, fp32.
// One block = one (b,h) x 64-query tile.  256 threads: 4 threads per query,
// each owning 16 head dims.  Online softmax, chunks of 32 keys.
// grid = (S/64 = 32, B*H = 64)
// ---------------------------------------------------------------------------
__global__ __launch_bounds__(256) void flash_kernel()
{
    __shared__ float Ks[64][68];
    __shared__ float Vs[64][68];

    const int tid  = threadIdx.x;
    const int q    = tid >> 2;     // 0..63 local query
    const int part = tid & 3;      // 0..3  (16 dims each)
    const int qt   = blockIdx.x;   // query tile
    const int bh   = blockIdx.y;   // b*H + h

    // Load Q row slice into registers, pre-scaled by 1/sqrt(HD) = 0.125
    const float* Qp = g_Q + ((size_t)bh * S_ + qt * 64 + q) * HD_ + part * 16;
    float qreg[16];
    #pragma unroll
    for (int i = 0; i < 4; ++i) {
        float4 v = *reinterpret_cast<const float4*>(Qp + i * 4);
        qreg[i * 4 + 0] = v.x * 0.125f;
        qreg[i * 4 + 1] = v.y * 0.125f;
        qreg[i * 4 + 2] = v.z * 0.125f;
        qreg[i * 4 + 3] = v.w * 0.125f;
    }

    float acc[16];
    #pragma unroll
    for (int i = 0; i < 16; ++i) acc[i] = 0.0f;
    float m = -1e30f, l = 0.0f;

    for (int kt = 0; kt <= qt; ++kt) {
        const float* Kp = g_K + ((size_t)bh * S_ + kt * 64) * HD_;
        const float* Vp = g_V + ((size_t)bh * S_ + kt * 64) * HD_;
        #pragma unroll
        for (int i = 0; i < 4; ++i) {
            int f   = tid + i * 256;    // 0..1023
            int row = f >> 4;           // 0..63
            int c4  = f & 15;           // float4 along hd
            *reinterpret_cast<float4*>(&Ks[row][c4 * 4]) =
                *reinterpret_cast<const float4*>(Kp + row * 64 + c4 * 4);
            *reinterpret_cast<float4*>(&Vs[row][c4 * 4]) =
                *reinterpret_cast<const float4*>(Vp + row * 64 + c4 * 4);
        }
        __syncthreads();

        #pragma unroll
        for (int c = 0; c < 2; ++c) {
            float sc[32];
            // partial dot (16 dims) for 32 keys
            #pragma unroll
            for (int k = 0; k < 32; ++k) {
                const float* kr = &Ks[c * 32 + k][part * 16];
                float4 k0 = *reinterpret_cast<const float4*>(kr);
                float4 k1 = *reinterpret_cast<const float4*>(kr + 4);
                float4 k2 = *reinterpret_cast<const float4*>(kr + 8);
                float4 k3 = *reinterpret_cast<const float4*>(kr + 12);
                float d = qreg[0] * k0.x + qreg[1] * k0.y + qreg[2] * k0.z + qreg[3] * k0.w
                        + qreg[4] * k1.x + qreg[5] * k1.y + qreg[6] * k1.z + qreg[7] * k1.w
                        + qreg[8] * k2.x + qreg[9] * k2.y + qreg[10] * k2.z + qreg[11] * k2.w
                        + qreg[12] * k3.x + qreg[13] * k3.y + qreg[14] * k3.z + qreg[15] * k3.w;
                sc[k] = d;
            }
            // reduce across the 4 lanes of this query
            #pragma unroll
            for (int k = 0; k < 32; ++k) {
                sc[k] += __shfl_xor_sync(0xffffffffu, sc[k], 1);
                sc[k] += __shfl_xor_sync(0xffffffffu, sc[k], 2);
            }
            // causal mask (only the diagonal tile needs it)
            if (kt == qt) {
                #pragma unroll
                for (int k = 0; k < 32; ++k)
                    if (c * 32 + k > q) sc[k] = -1e30f;
            }
            // online softmax update
            float tm = -1e30f;
            #pragma unroll
            for (int k = 0; k < 32; ++k) tm = fmaxf(tm, sc[k]);
            float mn   = fmaxf(m, tm);
            float corr = __expf(m - mn);
            l *= corr;
            #pragma unroll
            for (int d = 0; d < 16; ++d) acc[d] *= corr;
            #pragma unroll
            for (int k = 0; k < 32; ++k) {
                float p = __expf(sc[k] - mn);
                l += p;
                const float* vr = &Vs[c * 32 + k][part * 16];
                float4 v0 = *reinterpret_cast<const float4*>(vr);
                float4 v1 = *reinterpret_cast<const float4*>(vr + 4);
                float4 v2 = *reinterpret_cast<const float4*>(vr + 8);
                float4 v3 = *reinterpret_cast<const float4*>(vr + 12);
                acc[0]  += p * v0.x;  acc[1]  += p * v0.y;
                acc[2]  += p * v0.z;  acc[3]  += p * v0.w;
                acc[4]  += p * v1.x;  acc[5]  += p * v1.y;
                acc[6]  += p * v1.z;  acc[7]  += p * v1.w;
                acc[8]  += p * v2.x;  acc[9]  += p * v2.y;
                acc[10] += p * v2.z;  acc[11] += p * v2.w;
                acc[12] += p * v3.x;  acc[13] += p * v3.y;
                acc[14] += p * v3.z;  acc[15] += p * v3.w;
            }
            m = mn;
        }
        __syncthreads();
    }

    // Normalize and write ctx in (b, s, h*HD + hd) layout
    const float inv = 1.0f / l;
    const int b = bh >> 4, h = bh & 15;
    float* op = g_ctx + ((size_t)(b * S_) + qt * 64 + q) * DOUT + h * HD_ + part * 16;
    #pragma unroll
    for (int i = 0; i < 4; ++i) {
        float4 v = {acc[i * 4 + 0] * inv, acc[i * 4 + 1] * inv,
                    acc[i * 4 + 2] * inv, acc[i * 4 + 3] * inv};
        *reinterpret_cast<float4*>(op + i * 4) = v;
    }
}

// ---------------------------------------------------------------------------
// Kernel 3: output projection.  out = ctx @ Wo^T + bo
// Y[m][n] = sum_k ctx[m][k] * Wo[n][k] + bo[n]
// BM=128, BN=128, BK=16, 256 threads, 8x8 per thread.  grid = (64, 8)
// ---------------------------------------------------------------------------
__global__ __launch_bounds__(256) void oproj_kernel(
    const float* __restrict__ Wo,
    const float* __restrict__ bo,
    float* __restrict__ out)
{
    __shared__ float As[16][128];
    __shared__ float Bs[16][128];

    const int tid = threadIdx.x;
    const int ty  = tid >> 4;
    const int tx  = tid & 15;
    const int rowBase = blockIdx.x * 128;
    const int nBase   = blockIdx.y * 128;

    float acc[8][8];
    #pragma unroll
    for (int i = 0; i < 8; ++i)
        #pragma unroll
        for (int j = 0; j < 8; ++j) acc[i][j] = 0.0f;

    for (int kb = 0; kb < DOUT; kb += 16) {
        // A tile from g_ctx
        #pragma unroll
        for (int i = 0; i < 2; ++i) {
            int f  = tid + i * 256;
            int mm = f >> 2;
            int kq = f & 3;
            float4 v = *reinterpret_cast<const float4*>(
                &g_ctx[(size_t)(rowBase + mm) * DOUT + kb + kq * 4]);
            As[kq * 4 + 0][mm] = v.x;
            As[kq * 4 + 1][mm] = v.y;
            As[kq * 4 + 2][mm] = v.z;
            As[kq * 4 + 3][mm] = v.w;
        }
        // B tile: Bs[k][n] = Wo[nBase+n][kb+k]  (read along k, coalesced)
        #pragma unroll
        for (int i = 0; i < 2; ++i) {
            int f  = tid + i * 256;      // 0..511
            int n  = f >> 2;             // 0..127
            int kq = f & 3;
            float4 v = *reinterpret_cast<const float4*>(
                &Wo[(size_t)(nBase + n) * DOUT + kb + kq * 4]);
            Bs[kq * 4 + 0][n] = v.x;
            Bs[kq * 4 + 1][n] = v.y;
            Bs[kq * 4 + 2][n] = v.z;
            Bs[kq * 4 + 3][n] = v.w;
        }
        __syncthreads();

        #pragma unroll
        for (int kk = 0; kk < 16; ++kk) {
            float4 a0 = *reinterpret_cast<const float4*>(&As[kk][ty * 8]);
            float4 a1 = *reinterpret_cast<const float4*>(&As[kk][ty * 8 + 4]);
            float4 b0 = *reinterpret_cast<const float4*>(&Bs[kk][tx * 8]);
            float4 b1 = *reinterpret_cast<const float4*>(&Bs[kk][tx * 8 + 4]);
            float a[8] = {a0.x, a0.y, a0.z, a0.w, a1.x, a1.y, a1.z, a1.w};
            float b[8] = {b0.x, b0.y, b0.z, b0.w, b1.x, b1.y, b1.z, b1.w};
            #pragma unroll
            for (int i = 0; i < 8; ++i)
                #pragma unroll
                for (int j = 0; j < 8; ++j)
                    acc[i][j] += a[i] * b[j];
        }
        __syncthreads();
    }

    float4 bias0 = *reinterpret_cast<const float4*>(&bo[nBase + tx * 8]);
    float4 bias1 = *reinterpret_cast<const float4*>(&bo[nBase + tx * 8 + 4]);
    #pragma unroll
    for (int i = 0; i < 8; ++i) {
        int r = rowBase + ty * 8 + i;
        float4 v0 = {acc[i][0] + bias0.x, acc[i][1] + bias0.y,
                     acc[i][2] + bias0.z, acc[i][3] + bias0.w};
        float4 v1 = {acc[i][4] + bias1.x, acc[i][5] + bias1.y,
                     acc[i][6] + bias1.z, acc[i][7] + bias1.w};
        *reinterpret_cast<float4*>(&out[(size_t)r * DOUT + nBase + tx * 8])     = v0;
        *reinterpret_cast<float4*>(&out[(size_t)r * DOUT + nBase + tx * 8 + 4]) = v1;
    }
}

// ---------------------------------------------------------------------------
extern "C" void kernel_launch(void* const* d_in, const int* in_sizes, int n_in,
                              void* d_out, int out_size)
{
    const float* x  = (const float*)d_in[0];
    const float* Wq = (const float*)d_in[1];
    const float* Wk = (const float*)d_in[2];
    const float* Wv = (const float*)d_in[3];
    const float* Wo = (const float*)d_in[4];
    const float* bo = (const float*)d_in[5];
    float* out = (float*)d_out;

    qkv_kernel<<<dim3(64, 24), 256>>>(x, Wq, Wk, Wv);
    flash_kernel<<<dim3(32, 64), 256>>>();
    oproj_kernel<<<dim3(64, 8), 256>>>(Wo, bo, out);
}

// round 3
// speedup vs baseline: 6.2785x; 6.2785x over previous
#include <cuda_runtime.h>
#include <cstdint>

#define B_   4
#define S_   2048
#define DIN  1024
#define DOUT 1024
#define H_   16
#define HD_  64
#define KDIM 1024

// ---------------------------------------------------------------------------
// Scratch (module-scope device arrays: allowed; no runtime allocation)
// ---------------------------------------------------------------------------
__device__ float g_Q[B_ * H_ * S_ * HD_];    // (b,h,s,hd)
__device__ float g_K[B_ * H_ * S_ * HD_];
__device__ float g_V[B_ * H_ * S_ * HD_];
__device__ float g_ctx[B_ * S_ * DOUT];      // (b,s,d)
__device__ float g_WT[3 * DIN * DOUT];       // Wq^T, Wk^T, Wv^T  ([n][k])

// ---------------------------------------------------------------------------
// tf32 helpers (baseline PTX, works through compute_103)
// ---------------------------------------------------------------------------
__device__ __forceinline__ uint32_t f2tf32(float f) {
    uint32_t r;
    asm("cvt.rna.tf32.f32 %0, %1;" : "=r"(r) : "f"(f));
    return r;
}

// D += A*B, m16n8k8 tf32 (fp32 accumulate)
__device__ __forceinline__ void mma_tf32(float* d,
    uint32_t a0, uint32_t a1, uint32_t a2, uint32_t a3,
    uint32_t b0, uint32_t b1)
{
    asm volatile(
        "mma.sync.aligned.m16n8k8.row.col.f32.tf32.tf32.f32 "
        "{%0,%1,%2,%3}, {%4,%5,%6,%7}, {%8,%9}, {%0,%1,%2,%3};"
        : "+f"(d[0]), "+f"(d[1]), "+f"(d[2]), "+f"(d[3])
        : "r"(a0), "r"(a1), "r"(a2), "r"(a3), "r"(b0), "r"(b1));
}

// ---------------------------------------------------------------------------
// Kernel 0: transpose Wq/Wk/Wv ([K,N] -> [N,K]) into g_WT
// grid (32, 32, 3), block (32, 8)
// ---------------------------------------------------------------------------
__global__ __launch_bounds__(256) void transpose3_kernel(
    const float* __restrict__ Wq,
    const float* __restrict__ Wk,
    const float* __restrict__ Wv)
{
    __shared__ float t[32][33];
    const float* src = (blockIdx.z == 0) ? Wq : (blockIdx.z == 1) ? Wk : Wv;
    float* dst = g_WT + (size_t)blockIdx.z * DIN * DOUT;
    const int bx = blockIdx.x * 32, by = blockIdx.y * 32;
    const int tx = threadIdx.x, ty = threadIdx.y;
    #pragma unroll
    for (int i = 0; i < 32; i += 8)
        t[ty + i][tx] = src[(size_t)(by + ty + i) * DOUT + bx + tx];
    __syncthreads();
    #pragma unroll
    for (int i = 0; i < 32; i += 8)
        dst[(size_t)(bx + ty + i) * DIN + by + tx] = t[tx][ty + i];
}

// ---------------------------------------------------------------------------
// GEMM via mma.sync tf32: C[128x128] = A[128xK] * B[128xK]^T
// 256 threads, 8 warps (2m x 4n), warp tile 64x32, BK=32.
// Smem: As[m][k] pad 36, Bs[n][k] pad 36  (fragment LDS conflict-free).
// ---------------------------------------------------------------------------
#define GPAD 36

__device__ __forceinline__ void gemm_tc_mainloop(
    const float* __restrict__ Asrc, const float* __restrict__ Bsrc,
    uint32_t* As, uint32_t* Bs, float acc[4][4][4],
    int tid, int wm, int wn, int g, int q)
{
    #pragma unroll
    for (int mt = 0; mt < 4; ++mt)
        #pragma unroll
        for (int nt = 0; nt < 4; ++nt)
            #pragma unroll
            for (int j = 0; j < 4; ++j) acc[mt][nt][j] = 0.0f;

    for (int ch = 0; ch < KDIM / 32; ++ch) {
        #pragma unroll
        for (int i = 0; i < 4; ++i) {
            int f   = tid + i * 256;     // 0..1023
            int row = f >> 3;            // 0..127
            int k4  = f & 7;             // float4 along the 32-float chunk
            float4 va = *reinterpret_cast<const float4*>(
                Asrc + (size_t)row * KDIM + ch * 32 + k4 * 4);
            float4 vb = *reinterpret_cast<const float4*>(
                Bsrc + (size_t)row * KDIM + ch * 32 + k4 * 4);
            uint32_t* pa = &As[row * GPAD + k4 * 4];
            uint32_t* pb = &Bs[row * GPAD + k4 * 4];
            pa[0] = f2tf32(va.x); pa[1] = f2tf32(va.y);
            pa[2] = f2tf32(va.z); pa[3] = f2tf32(va.w);
            pb[0] = f2tf32(vb.x); pb[1] = f2tf32(vb.y);
            pb[2] = f2tf32(vb.z); pb[3] = f2tf32(vb.w);
        }
        __syncthreads();

        #pragma unroll
        for (int ks = 0; ks < 4; ++ks) {
            uint32_t a[4][4], b[4][2];
            #pragma unroll
            for (int mt = 0; mt < 4; ++mt) {
                int m0 = wm * 64 + mt * 16 + g;
                a[mt][0] = As[m0 * GPAD + ks * 8 + q];
                a[mt][1] = As[(m0 + 8) * GPAD + ks * 8 + q];
                a[mt][2] = As[m0 * GPAD + ks * 8 + q + 4];
                a[mt][3] = As[(m0 + 8) * GPAD + ks * 8 + q + 4];
            }
            #pragma unroll
            for (int nt = 0; nt < 4; ++nt) {
                int n0 = wn * 32 + nt * 8 + g;
                b[nt][0] = Bs[n0 * GPAD + ks * 8 + q];
                b[nt][1] = Bs[n0 * GPAD + ks * 8 + q + 4];
            }
            #pragma unroll
            for (int mt = 0; mt < 4; ++mt)
                #pragma unroll
                for (int nt = 0; nt < 4; ++nt)
                    mma_tf32(acc[mt][nt], a[mt][0], a[mt][1], a[mt][2], a[mt][3],
                             b[nt][0], b[nt][1]);
        }
        __syncthreads();
    }
}

// ---------------------------------------------------------------------------
// Kernel 1: QKV projection.  grid (64, 24), 256 threads.
// Output scattered into (b,h,s,hd).
// ---------------------------------------------------------------------------
__global__ __launch_bounds__(256) void qkv_tc_kernel(const float* __restrict__ x)
{
    __shared__ uint32_t As[128 * GPAD];
    __shared__ uint32_t Bs[128 * GPAD];

    const int tid = threadIdx.x;
    const int wid = tid >> 5, lane = tid & 31;
    const int g = lane >> 2, q = lane & 3;
    const int wm = wid >> 2, wn = wid & 3;   // 2m x 4n

    const int rowBase = blockIdx.x * 128;
    const int n0glob  = blockIdx.y * 128;    // 0..3071 in steps of 128
    const int w       = n0glob >> 10;        // which of Wq/Wk/Wv
    const int nw      = n0glob & 1023;

    float acc[4][4][4];
    gemm_tc_mainloop(x + (size_t)rowBase * KDIM,
                     g_WT + (size_t)n0glob * KDIM,
                     As, Bs, acc, tid, wm, wn, g, q);

    float* obuf = (w == 0) ? g_Q : (w == 1) ? g_K : g_V;
    #pragma unroll
    for (int mt = 0; mt < 4; ++mt) {
        int m0 = rowBase + wm * 64 + mt * 16 + g;
        int b0 = m0 >> 11, s0 = m0 & 2047;
        int m1 = m0 + 8;
        int b1 = m1 >> 11, s1 = m1 & 2047;
        #pragma unroll
        for (int nt = 0; nt < 4; ++nt) {
            int n  = nw + wn * 32 + nt * 8 + 2 * q;
            int h  = n >> 6, hd = n & 63;
            float2 v0 = {acc[mt][nt][0], acc[mt][nt][1]};
            float2 v1 = {acc[mt][nt][2], acc[mt][nt][3]};
            *reinterpret_cast<float2*>(
                &obuf[(((size_t)(b0 * H_ + h) * S_) + s0) * HD_ + hd]) = v0;
            *reinterpret_cast<float2*>(
                &obuf[(((size_t)(b1 * H_ + h) * S_) + s1) * HD_ + hd]) = v1;
        }
    }
}

// ---------------------------------------------------------------------------
// Kernel 3: output projection.  out = ctx @ Wo^T + bo.  grid (64, 8).
// ---------------------------------------------------------------------------
__global__ __launch_bounds__(256) void oproj_tc_kernel(
    const float* __restrict__ Wo,
    const float* __restrict__ bo,
    float* __restrict__ out)
{
    __shared__ uint32_t As[128 * GPAD];
    __shared__ uint32_t Bs[128 * GPAD];

    const int tid = threadIdx.x;
    const int wid = tid >> 5, lane = tid & 31;
    const int g = lane >> 2, q = lane & 3;
    const int wm = wid >> 2, wn = wid & 3;

    const int rowBase = blockIdx.x * 128;
    const int n0      = blockIdx.y * 128;

    float acc[4][4][4];
    gemm_tc_mainloop(g_ctx + (size_t)rowBase * KDIM,
                     Wo + (size_t)n0 * KDIM,
                     As, Bs, acc, tid, wm, wn, g, q);

    #pragma unroll
    for (int mt = 0; mt < 4; ++mt) {
        int m0 = rowBase + wm * 64 + mt * 16 + g;
        #pragma unroll
        for (int nt = 0; nt < 4; ++nt) {
            int n = n0 + wn * 32 + nt * 8 + 2 * q;
            float2 bias = *reinterpret_cast<const float2*>(&bo[n]);
            float2 v0 = {acc[mt][nt][0] + bias.x, acc[mt][nt][1] + bias.y};
            float2 v1 = {acc[mt][nt][2] + bias.x, acc[mt][nt][3] + bias.y};
            *reinterpret_cast<float2*>(&out[(size_t)m0 * DOUT + n])       = v0;
            *reinterpret_cast<float2*>(&out[(size_t)(m0 + 8) * DOUT + n]) = v1;
        }
    }
}

// ---------------------------------------------------------------------------
// Kernel 2: causal flash attention via mma.sync tf32.
// 128 queries per block, 8 warps x 16 rows.  Q in registers (A-frags),
// K smem pad 68, V smem pad 72.  P converted C-frag -> A-frag via shuffles.
// grid (16, 64), 256 threads.
// ---------------------------------------------------------------------------
#define KPAD 68
#define VPAD 72

__global__ __launch_bounds__(256) void flash_tc_kernel()
{
    __shared__ uint32_t Ks[64 * KPAD];
    __shared__ uint32_t Vs[64 * VPAD];

    const int tid  = threadIdx.x;
    const int wid  = tid >> 5, lane = tid & 31;
    const int g    = lane >> 2, q = lane & 3;
    const int qt   = blockIdx.x;             // 16 query tiles of 128
    const int bh   = blockIdx.y;
    const int qbase = qt * 128;
    const int mrow0 = qbase + wid * 16 + g;  // rows: mrow0, mrow0+8

    // Q A-fragments, pre-scaled by 1/sqrt(64)
    uint32_t qf[8][4];
    {
        const float* Qp = g_Q + ((size_t)bh * S_ + mrow0) * HD_;
        #pragma unroll
        for (int ks = 0; ks < 8; ++ks) {
            qf[ks][0] = f2tf32(Qp[ks * 8 + q] * 0.125f);
            qf[ks][1] = f2tf32(Qp[8 * HD_ + ks * 8 + q] * 0.125f);
            qf[ks][2] = f2tf32(Qp[ks * 8 + q + 4] * 0.125f);
            qf[ks][3] = f2tf32(Qp[8 * HD_ + ks * 8 + q + 4] * 0.125f);
        }
    }

    float o[8][4];
    #pragma unroll
    for (int nt = 0; nt < 8; ++nt)
        #pragma unroll
        for (int j = 0; j < 4; ++j) o[nt][j] = 0.0f;
    float mA = -1e30f, mB = -1e30f, lA = 0.0f, lB = 0.0f;

    const int nch = 2 * qt + 2;
    for (int c = 0; c < nch; ++c) {
        // Load K/V chunk (64 keys x 64 hd) into smem, cvt to tf32
        const float* Kp = g_K + ((size_t)bh * S_ + c * 64) * HD_;
        const float* Vp = g_V + ((size_t)bh * S_ + c * 64) * HD_;
        #pragma unroll
        for (int i = 0; i < 4; ++i) {
            int f   = tid + i * 256;     // 0..1023
            int row = f >> 4;            // key 0..63
            int c4  = f & 15;            // float4 along hd
            float4 kv = *reinterpret_cast<const float4*>(Kp + row * HD_ + c4 * 4);
            float4 vv = *reinterpret_cast<const float4*>(Vp + row * HD_ + c4 * 4);
            uint32_t* pk = &Ks[row * KPAD + c4 * 4];
            uint32_t* pv = &Vs[row * VPAD + c4 * 4];
            pk[0] = f2tf32(kv.x); pk[1] = f2tf32(kv.y);
            pk[2] = f2tf32(kv.z); pk[3] = f2tf32(kv.w);
            pv[0] = f2tf32(vv.x); pv[1] = f2tf32(vv.y);
            pv[2] = f2tf32(vv.z); pv[3] = f2tf32(vv.w);
        }
        __syncthreads();

        // S = Q K^T  (m=128 q, n=64 keys, k=64 hd)
        float s[8][4];
        #pragma unroll
        for (int nt = 0; nt < 8; ++nt)
            #pragma unroll
            for (int j = 0; j < 4; ++j) s[nt][j] = 0.0f;
        #pragma unroll
        for (int ks = 0; ks < 8; ++ks) {
            #pragma unroll
            for (int nt = 0; nt < 8; ++nt) {
                uint32_t b0 = Ks[(nt * 8 + g) * KPAD + ks * 8 + q];
                uint32_t b1 = Ks[(nt * 8 + g) * KPAD + ks * 8 + q + 4];
                mma_tf32(s[nt], qf[ks][0], qf[ks][1], qf[ks][2], qf[ks][3], b0, b1);
            }
        }

        // Causal mask — only the last two chunks can violate causality
        if (c >= 2 * qt) {
            int kb = c * 64;
            #pragma unroll
            for (int nt = 0; nt < 8; ++nt) {
                int col = kb + nt * 8 + 2 * q;
                if (col     > mrow0)     s[nt][0] = -1e30f;
                if (col + 1 > mrow0)     s[nt][1] = -1e30f;
                if (col     > mrow0 + 8) s[nt][2] = -1e30f;
                if (col + 1 > mrow0 + 8) s[nt][3] = -1e30f;
            }
        }

        // Row max (rows A = mrow0, B = mrow0+8)
        float tmA = -1e30f, tmB = -1e30f;
        #pragma unroll
        for (int nt = 0; nt < 8; ++nt) {
            tmA = fmaxf(tmA, fmaxf(s[nt][0], s[nt][1]));
            tmB = fmaxf(tmB, fmaxf(s[nt][2], s[nt][3]));
        }
        tmA = fmaxf(tmA, __shfl_xor_sync(0xffffffffu, tmA, 1));
        tmA = fmaxf(tmA, __shfl_xor_sync(0xffffffffu, tmA, 2));
        tmB = fmaxf(tmB, __shfl_xor_sync(0xffffffffu, tmB, 1));
        tmB = fmaxf(tmB, __shfl_xor_sync(0xffffffffu, tmB, 2));
        float mnA = fmaxf(mA, tmA), mnB = fmaxf(mB, tmB);
        float corrA = __expf(mA - mnA), corrB = __expf(mB - mnB);
        lA *= corrA; lB *= corrB;
        #pragma unroll
        for (int nt = 0; nt < 8; ++nt) {
            o[nt][0] *= corrA; o[nt][1] *= corrA;
            o[nt][2] *= corrB; o[nt][3] *= corrB;
        }

        // P = exp(S - mn), converted to tf32 in place (bits in s[])
        float sumA = 0.0f, sumB = 0.0f;
        #pragma unroll
        for (int nt = 0; nt < 8; ++nt) {
            float p0 = __expf(s[nt][0] - mnA);
            float p1 = __expf(s[nt][1] - mnA);
            float p2 = __expf(s[nt][2] - mnB);
            float p3 = __expf(s[nt][3] - mnB);
            sumA += p0 + p1; sumB += p2 + p3;
            s[nt][0] = __uint_as_float(f2tf32(p0));
            s[nt][1] = __uint_as_float(f2tf32(p1));
            s[nt][2] = __uint_as_float(f2tf32(p2));
            s[nt][3] = __uint_as_float(f2tf32(p3));
        }
        sumA += __shfl_xor_sync(0xffffffffu, sumA, 1);
        sumA += __shfl_xor_sync(0xffffffffu, sumA, 2);
        sumB += __shfl_xor_sync(0xffffffffu, sumB, 1);
        sumB += __shfl_xor_sync(0xffffffffu, sumB, 2);
        lA += sumA; lB += sumB;
        mA = mnA; mB = mnB;

        // O += P V  (m=128 q, n=64 hd, k=64 keys); P A-frags via shuffles
        const int src0 = (lane & ~3) | (q >> 1);
        const int src2 = src0 + 2;
        #pragma unroll
        for (int ks = 0; ks < 8; ++ks) {
            float v00 = __shfl_sync(0xffffffffu, s[ks][0], src0);
            float v01 = __shfl_sync(0xffffffffu, s[ks][1], src0);
            float v20 = __shfl_sync(0xffffffffu, s[ks][2], src0);
            float v21 = __shfl_sync(0xffffffffu, s[ks][3], src0);
            float w00 = __shfl_sync(0xffffffffu, s[ks][0], src2);
            float w01 = __shfl_sync(0xffffffffu, s[ks][1], src2);
            float w20 = __shfl_sync(0xffffffffu, s[ks][2], src2);
            float w21 = __shfl_sync(0xffffffffu, s[ks][3], src2);
            uint32_t a0 = __float_as_uint((q & 1) ? v01 : v00);
            uint32_t a1 = __float_as_uint((q & 1) ? v21 : v20);
            uint32_t a2 = __float_as_uint((q & 1) ? w01 : w00);
            uint32_t a3 = __float_as_uint((q & 1) ? w21 : w20);
            #pragma unroll
            for (int nt = 0; nt < 8; ++nt) {
                uint32_t b0 = Vs[(ks * 8 + q) * VPAD + nt * 8 + g];
                uint32_t b1 = Vs[(ks * 8 + q + 4) * VPAD + nt * 8 + g];
                mma_tf32(o[nt], a0, a1, a2, a3, b0, b1);
            }
        }
        __syncthreads();
    }

    // Normalize + write ctx (b, s, h*64 + hd)
    const float invA = 1.0f / lA, invB = 1.0f / lB;
    const int b = bh >> 4, h = bh & 15;
    float* base0 = g_ctx + ((size_t)(b * S_) + mrow0) * DOUT + h * HD_;
    float* base1 = base0 + (size_t)8 * DOUT;
    #pragma unroll
    for (int nt = 0; nt < 8; ++nt) {
        int col = nt * 8 + 2 * q;
        float2 v0 = {o[nt][0] * invA, o[nt][1] * invA};
        float2 v1 = {o[nt][2] * invB, o[nt][3] * invB};
        *reinterpret_cast<float2*>(base0 + col) = v0;
        *reinterpret_cast<float2*>(base1 + col) = v1;
    }
}

// ---------------------------------------------------------------------------
extern "C" void kernel_launch(void* const* d_in, const int* in_sizes, int n_in,
                              void* d_out, int out_size)
{
    const float* x  = (const float*)d_in[0];
    const float* Wq = (const float*)d_in[1];
    const float* Wk = (const float*)d_in[2];
    const float* Wv = (const float*)d_in[3];
    const float* Wo = (const float*)d_in[4];
    const float* bo = (const float*)d_in[5];
    float* out = (float*)d_out;

    transpose3_kernel<<<dim3(32, 32, 3), dim3(32, 8)>>>(Wq, Wk, Wv);
    qkv_tc_kernel<<<dim3(64, 24), 256>>>(x);
    flash_tc_kernel<<<dim3(16, 64), 256>>>();
    oproj_tc_kernel<<<dim3(64, 8), 256>>>(Wo, bo, out);
}

// round 4
// speedup vs baseline: 6.9654x; 1.1094x over previous
#include <cuda_runtime.h>
#include <cstdint>

#define B_   4
#define S_   2048
#define DIN  1024
#define DOUT 1024
#define H_   16
#define HD_  64
#define KDIM 1024

// ---------------------------------------------------------------------------
// Scratch (module-scope device arrays: allowed; no runtime allocation)
// ---------------------------------------------------------------------------
__device__ float g_Q[B_ * H_ * S_ * HD_];    // (b,h,s,hd)   tf32-rounded
__device__ float g_K[B_ * H_ * S_ * HD_];
__device__ float g_V[B_ * H_ * S_ * HD_];
__device__ float g_ctx[B_ * S_ * DOUT];      // (b,s,d)      tf32-rounded
__device__ float g_WT[3 * DIN * DOUT];       // Wq^T,Wk^T,Wv^T [n][k] tf32-rounded
__device__ float g_X [B_ * S_ * DIN];        // x, tf32-rounded
__device__ float g_Wo[DOUT * DOUT];          // Wo, tf32-rounded

// ---------------------------------------------------------------------------
// helpers
// ---------------------------------------------------------------------------
__device__ __forceinline__ uint32_t f2tf32(float f) {
    uint32_t r;
    asm("cvt.rna.tf32.f32 %0, %1;" : "=r"(r) : "f"(f));
    return r;
}
__device__ __forceinline__ float rtf(float f) { return __uint_as_float(f2tf32(f)); }

__device__ __forceinline__ uint32_t smem_u32(const void* p) {
    uint32_t a;
    asm("{ .reg .u64 t; cvta.to.shared.u64 t, %1; cvt.u32.u64 %0, t; }"
        : "=r"(a) : "l"(p));
    return a;
}
__device__ __forceinline__ void cp16(uint32_t dst, const void* src) {
    asm volatile("cp.async.cg.shared.global [%0], [%1], 16;"
                 :: "r"(dst), "l"(src) : "memory");
}
#define CP_COMMIT() asm volatile("cp.async.commit_group;" ::: "memory")
#define CP_WAIT(n)  asm volatile("cp.async.wait_group %0;" :: "n"(n) : "memory")

// D += A*B, m16n8k8 tf32 (fp32 accumulate)
__device__ __forceinline__ void mma_tf32(float* d,
    uint32_t a0, uint32_t a1, uint32_t a2, uint32_t a3,
    uint32_t b0, uint32_t b1)
{
    asm volatile(
        "mma.sync.aligned.m16n8k8.row.col.f32.tf32.tf32.f32 "
        "{%0,%1,%2,%3}, {%4,%5,%6,%7}, {%8,%9}, {%0,%1,%2,%3};"
        : "+f"(d[0]), "+f"(d[1]), "+f"(d[2]), "+f"(d[3])
        : "r"(a0), "r"(a1), "r"(a2), "r"(a3), "r"(b0), "r"(b1));
}

// ---------------------------------------------------------------------------
// Kernel P: pre-round x -> g_X and Wo -> g_Wo (tf32 rna)
// one float4 per thread.  total f4 = (8388608 + 1048576)/4 = 2359296
// ---------------------------------------------------------------------------
#define XF4 (B_ * S_ * DIN / 4)
__global__ __launch_bounds__(256) void cvt_pre_kernel(
    const float* __restrict__ x, const float* __restrict__ Wo)
{
    int i = blockIdx.x * 256 + threadIdx.x;
    if (i < XF4) {
        float4 v = *reinterpret_cast<const float4*>(x + (size_t)i * 4);
        float4 r = {rtf(v.x), rtf(v.y), rtf(v.z), rtf(v.w)};
        *reinterpret_cast<float4*>(g_X + (size_t)i * 4) = r;
    } else {
        int j = i - XF4;
        float4 v = *reinterpret_cast<const float4*>(Wo + (size_t)j * 4);
        float4 r = {rtf(v.x), rtf(v.y), rtf(v.z), rtf(v.w)};
        *reinterpret_cast<float4*>(g_Wo + (size_t)j * 4) = r;
    }
}

// ---------------------------------------------------------------------------
// Kernel 0: transpose Wq/Wk/Wv ([K,N] -> [N,K]) + tf32 round, into g_WT
// grid (32, 32, 3), block (32, 8)
// ---------------------------------------------------------------------------
__global__ __launch_bounds__(256) void transpose3_kernel(
    const float* __restrict__ Wq,
    const float* __restrict__ Wk,
    const float* __restrict__ Wv)
{
    __shared__ float t[32][33];
    const float* src = (blockIdx.z == 0) ? Wq : (blockIdx.z == 1) ? Wk : Wv;
    float* dst = g_WT + (size_t)blockIdx.z * DIN * DOUT;
    const int bx = blockIdx.x * 32, by = blockIdx.y * 32;
    const int tx = threadIdx.x, ty = threadIdx.y;
    #pragma unroll
    for (int i = 0; i < 32; i += 8)
        t[ty + i][tx] = src[(size_t)(by + ty + i) * DOUT + bx + tx];
    __syncthreads();
    #pragma unroll
    for (int i = 0; i < 32; i += 8)
        dst[(size_t)(bx + ty + i) * DIN + by + tx] = rtf(t[tx][ty + i]);
}

// ---------------------------------------------------------------------------
// GEMM via mma.sync tf32: C[128x128] = A[128xK] * B[128xK]^T
// 256 threads, 8 warps (2m x 4n), warp tile 64x32, BK=32.
// Double-buffered cp.async; operands already tf32-rounded in gmem.
// Smem (dynamic): As[2][128*GPAD], Bs[2][128*GPAD]
// ---------------------------------------------------------------------------
#define GPAD  36
#define GSTGW (128 * GPAD)          // words per stage
#define GSTGB (GSTGW * 4)           // bytes per stage
#define NCH32 (KDIM / 32)

#define GEMM_ISSUE(ch, stage) do {                                          \
    _Pragma("unroll")                                                       \
    for (int i_ = 0; i_ < 4; ++i_) {                                        \
        int f_ = tid + i_ * 256, row_ = f_ >> 3, k4_ = f_ & 7;              \
        uint32_t off_ = (uint32_t)(stage) * GSTGB +                         \
                        (uint32_t)(row_ * GPAD + k4_ * 4) * 4u;             \
        cp16(uA + off_, Asrc + (size_t)row_ * KDIM + (ch) * 32 + k4_ * 4);  \
        cp16(uB + off_, Bsrc + (size_t)row_ * KDIM + (ch) * 32 + k4_ * 4);  \
    }                                                                       \
    CP_COMMIT();                                                            \
} while (0)

__device__ __forceinline__ void gemm_tc_mainloop(
    const float* __restrict__ Asrc, const float* __restrict__ Bsrc,
    uint32_t* As, uint32_t* Bs, float acc[4][4][4],
    int tid, int wm, int wn, int g, int q)
{
    #pragma unroll
    for (int mt = 0; mt < 4; ++mt)
        #pragma unroll
        for (int nt = 0; nt < 4; ++nt)
            #pragma unroll
            for (int j = 0; j < 4; ++j) acc[mt][nt][j] = 0.0f;

    const uint32_t uA = smem_u32(As), uB = smem_u32(Bs);

    GEMM_ISSUE(0, 0);
    for (int ch = 0; ch < NCH32; ++ch) {
        const int cur = ch & 1;
        if (ch + 1 < NCH32) { GEMM_ISSUE(ch + 1, cur ^ 1); CP_WAIT(1); }
        else                { CP_WAIT(0); }
        __syncthreads();

        const uint32_t* A0 = As + cur * GSTGW;
        const uint32_t* B0 = Bs + cur * GSTGW;
        #pragma unroll
        for (int ks = 0; ks < 4; ++ks) {
            uint32_t a[4][4], b[4][2];
            #pragma unroll
            for (int mt = 0; mt < 4; ++mt) {
                int m0 = wm * 64 + mt * 16 + g;
                a[mt][0] = A0[m0 * GPAD + ks * 8 + q];
                a[mt][1] = A0[(m0 + 8) * GPAD + ks * 8 + q];
                a[mt][2] = A0[m0 * GPAD + ks * 8 + q + 4];
                a[mt][3] = A0[(m0 + 8) * GPAD + ks * 8 + q + 4];
            }
            #pragma unroll
            for (int nt = 0; nt < 4; ++nt) {
                int n0 = wn * 32 + nt * 8 + g;
                b[nt][0] = B0[n0 * GPAD + ks * 8 + q];
                b[nt][1] = B0[n0 * GPAD + ks * 8 + q + 4];
            }
            #pragma unroll
            for (int mt = 0; mt < 4; ++mt)
                #pragma unroll
                for (int nt = 0; nt < 4; ++nt)
                    mma_tf32(acc[mt][nt], a[mt][0], a[mt][1], a[mt][2], a[mt][3],
                             b[nt][0], b[nt][1]);
        }
        __syncthreads();
    }
}

// ---------------------------------------------------------------------------
// Kernel 1: QKV projection.  grid (64, 24), 256 threads, dyn smem.
// Output tf32-rounded, scattered into (b,h,s,hd).
// ---------------------------------------------------------------------------
__global__ __launch_bounds__(256) void qkv_tc_kernel()
{
    extern __shared__ uint32_t dyn[];
    uint32_t* As = dyn;
    uint32_t* Bs = dyn + 2 * GSTGW;

    const int tid = threadIdx.x;
    const int wid = tid >> 5, lane = tid & 31;
    const int g = lane >> 2, q = lane & 3;
    const int wm = wid >> 2, wn = wid & 3;

    const int rowBase = blockIdx.x * 128;
    const int n0glob  = blockIdx.y * 128;
    const int w       = n0glob >> 10;
    const int nw      = n0glob & 1023;

    float acc[4][4][4];
    gemm_tc_mainloop(g_X + (size_t)rowBase * KDIM,
                     g_WT + (size_t)n0glob * KDIM,
                     As, Bs, acc, tid, wm, wn, g, q);

    float* obuf = (w == 0) ? g_Q : (w == 1) ? g_K : g_V;
    #pragma unroll
    for (int mt = 0; mt < 4; ++mt) {
        int m0 = rowBase + wm * 64 + mt * 16 + g;
        int b0 = m0 >> 11, s0 = m0 & 2047;
        int m1 = m0 + 8;
        int b1 = m1 >> 11, s1 = m1 & 2047;
        #pragma unroll
        for (int nt = 0; nt < 4; ++nt) {
            int n  = nw + wn * 32 + nt * 8 + 2 * q;
            int h  = n >> 6, hd = n & 63;
            float2 v0 = {rtf(acc[mt][nt][0]), rtf(acc[mt][nt][1])};
            float2 v1 = {rtf(acc[mt][nt][2]), rtf(acc[mt][nt][3])};
            *reinterpret_cast<float2*>(
                &obuf[(((size_t)(b0 * H_ + h) * S_) + s0) * HD_ + hd]) = v0;
            *reinterpret_cast<float2*>(
                &obuf[(((size_t)(b1 * H_ + h) * S_) + s1) * HD_ + hd]) = v1;
        }
    }
}

// ---------------------------------------------------------------------------
// Kernel 3: output projection.  out = ctx @ Wo^T + bo.  grid (64, 8), dyn smem.
// ---------------------------------------------------------------------------
__global__ __launch_bounds__(256) void oproj_tc_kernel(
    const float* __restrict__ bo, float* __restrict__ out)
{
    extern __shared__ uint32_t dyn[];
    uint32_t* As = dyn;
    uint32_t* Bs = dyn + 2 * GSTGW;

    const int tid = threadIdx.x;
    const int wid = tid >> 5, lane = tid & 31;
    const int g = lane >> 2, q = lane & 3;
    const int wm = wid >> 2, wn = wid & 3;

    const int rowBase = blockIdx.x * 128;
    const int n0      = blockIdx.y * 128;

    float acc[4][4][4];
    gemm_tc_mainloop(g_ctx + (size_t)rowBase * KDIM,
                     g_Wo + (size_t)n0 * KDIM,
                     As, Bs, acc, tid, wm, wn, g, q);

    #pragma unroll
    for (int mt = 0; mt < 4; ++mt) {
        int m0 = rowBase + wm * 64 + mt * 16 + g;
        #pragma unroll
        for (int nt = 0; nt < 4; ++nt) {
            int n = n0 + wn * 32 + nt * 8 + 2 * q;
            float2 bias = *reinterpret_cast<const float2*>(&bo[n]);
            float2 v0 = {acc[mt][nt][0] + bias.x, acc[mt][nt][1] + bias.y};
            float2 v1 = {acc[mt][nt][2] + bias.x, acc[mt][nt][3] + bias.y};
            *reinterpret_cast<float2*>(&out[(size_t)m0 * DOUT + n])       = v0;
            *reinterpret_cast<float2*>(&out[(size_t)(m0 + 8) * DOUT + n]) = v1;
        }
    }
}

// ---------------------------------------------------------------------------
// Kernel 2: causal flash attention via mma.sync tf32, cp.async double buffer.
// 128 queries per block, 8 warps x 16 rows.  grid (16, 64), 256 threads.
// Smem (dynamic): Ks[2][64*KPAD], Vs[2][64*VPAD]
// ---------------------------------------------------------------------------
#define KPAD 68
#define VPAD 72
#define KSTGW (64 * KPAD)
#define VSTGW (64 * VPAD)

#define FLASH_ISSUE(c, stage) do {                                           \
    const float* Kp_ = g_K + ((size_t)bh * S_ + (c) * 64) * HD_;             \
    const float* Vp_ = g_V + ((size_t)bh * S_ + (c) * 64) * HD_;             \
    _Pragma("unroll")                                                        \
    for (int i_ = 0; i_ < 4; ++i_) {                                         \
        int f_ = tid + i_ * 256, row_ = f_ >> 4, c4_ = f_ & 15;              \
        cp16(uK + (uint32_t)(stage) * (KSTGW * 4) +                          \
                 (uint32_t)(row_ * KPAD + c4_ * 4) * 4u,                     \
             Kp_ + row_ * HD_ + c4_ * 4);                                    \
        cp16(uV + (uint32_t)(stage) * (VSTGW * 4) +                          \
                 (uint32_t)(row_ * VPAD + c4_ * 4) * 4u,                     \
             Vp_ + row_ * HD_ + c4_ * 4);                                    \
    }                                                                        \
    CP_COMMIT();                                                             \
} while (0)

__global__ __launch_bounds__(256) void flash_tc_kernel()
{
    extern __shared__ uint32_t dyn[];
    uint32_t* Ksm = dyn;
    uint32_t* Vsm = dyn + 2 * KSTGW;

    const int tid  = threadIdx.x;
    const int wid  = tid >> 5, lane = tid & 31;
    const int g    = lane >> 2, q = lane & 3;
    const int qt   = (int)gridDim.x - 1 - (int)blockIdx.x;  // big tiles first
    const int bh   = blockIdx.y;
    const int mrow0 = qt * 128 + wid * 16 + g;

    const uint32_t uK = smem_u32(Ksm), uV = smem_u32(Vsm);

    // Q A-fragments (g_Q already tf32-rounded; *0.125 is exact)
    uint32_t qf[8][4];
    {
        const float* Qp = g_Q + ((size_t)bh * S_ + mrow0) * HD_;
        #pragma unroll
        for (int ks = 0; ks < 8; ++ks) {
            qf[ks][0] = __float_as_uint(Qp[ks * 8 + q] * 0.125f);
            qf[ks][1] = __float_as_uint(Qp[8 * HD_ + ks * 8 + q] * 0.125f);
            qf[ks][2] = __float_as_uint(Qp[ks * 8 + q + 4] * 0.125f);
            qf[ks][3] = __float_as_uint(Qp[8 * HD_ + ks * 8 + q + 4] * 0.125f);
        }
    }

    float o[8][4];
    #pragma unroll
    for (int nt = 0; nt < 8; ++nt)
        #pragma unroll
        for (int j = 0; j < 4; ++j) o[nt][j] = 0.0f;
    float mA = -1e30f, mB = -1e30f, lA = 0.0f, lB = 0.0f;

    const int nch = 2 * qt + 2;
    FLASH_ISSUE(0, 0);
    for (int c = 0; c < nch; ++c) {
        const int cur = c & 1;
        if (c + 1 < nch) { FLASH_ISSUE(c + 1, cur ^ 1); CP_WAIT(1); }
        else             { CP_WAIT(0); }
        __syncthreads();

        const uint32_t* K0 = Ksm + cur * KSTGW;
        const uint32_t* V0 = Vsm + cur * VSTGW;

        // S = Q K^T
        float s[8][4];
        #pragma unroll
        for (int nt = 0; nt < 8; ++nt)
            #pragma unroll
            for (int j = 0; j < 4; ++j) s[nt][j] = 0.0f;
        #pragma unroll
        for (int ks = 0; ks < 8; ++ks) {
            #pragma unroll
            for (int nt = 0; nt < 8; ++nt) {
                uint32_t b0 = K0[(nt * 8 + g) * KPAD + ks * 8 + q];
                uint32_t b1 = K0[(nt * 8 + g) * KPAD + ks * 8 + q + 4];
                mma_tf32(s[nt], qf[ks][0], qf[ks][1], qf[ks][2], qf[ks][3], b0, b1);
            }
        }

        if (c >= 2 * qt) {   // causal mask, last two chunks only
            int kb = c * 64;
            #pragma unroll
            for (int nt = 0; nt < 8; ++nt) {
                int col = kb + nt * 8 + 2 * q;
                if (col     > mrow0)     s[nt][0] = -1e30f;
                if (col + 1 > mrow0)     s[nt][1] = -1e30f;
                if (col     > mrow0 + 8) s[nt][2] = -1e30f;
                if (col + 1 > mrow0 + 8) s[nt][3] = -1e30f;
            }
        }

        float tmA = -1e30f, tmB = -1e30f;
        #pragma unroll
        for (int nt = 0; nt < 8; ++nt) {
            tmA = fmaxf(tmA, fmaxf(s[nt][0], s[nt][1]));
            tmB = fmaxf(tmB, fmaxf(s[nt][2], s[nt][3]));
        }
        tmA = fmaxf(tmA, __shfl_xor_sync(0xffffffffu, tmA, 1));
        tmA = fmaxf(tmA, __shfl_xor_sync(0xffffffffu, tmA, 2));
        tmB = fmaxf(tmB, __shfl_xor_sync(0xffffffffu, tmB, 1));
        tmB = fmaxf(tmB, __shfl_xor_sync(0xffffffffu, tmB, 2));
        float mnA = fmaxf(mA, tmA), mnB = fmaxf(mB, tmB);
        float corrA = __expf(mA - mnA), corrB = __expf(mB - mnB);
        lA *= corrA; lB *= corrB;
        #pragma unroll
        for (int nt = 0; nt < 8; ++nt) {
            o[nt][0] *= corrA; o[nt][1] *= corrA;
            o[nt][2] *= corrB; o[nt][3] *= corrB;
        }

        float sumA = 0.0f, sumB = 0.0f;
        #pragma unroll
        for (int nt = 0; nt < 8; ++nt) {
            float p0 = __expf(s[nt][0] - mnA);
            float p1 = __expf(s[nt][1] - mnA);
            float p2 = __expf(s[nt][2] - mnB);
            float p3 = __expf(s[nt][3] - mnB);
            sumA += p0 + p1; sumB += p2 + p3;
            s[nt][0] = __uint_as_float(f2tf32(p0));
            s[nt][1] = __uint_as_float(f2tf32(p1));
            s[nt][2] = __uint_as_float(f2tf32(p2));
            s[nt][3] = __uint_as_float(f2tf32(p3));
        }
        sumA += __shfl_xor_sync(0xffffffffu, sumA, 1);
        sumA += __shfl_xor_sync(0xffffffffu, sumA, 2);
        sumB += __shfl_xor_sync(0xffffffffu, sumB, 1);
        sumB += __shfl_xor_sync(0xffffffffu, sumB, 2);
        lA += sumA; lB += sumB;
        mA = mnA; mB = mnB;

        // O += P V   (P C-frag -> A-frag via shuffles)
        const int src0 = (lane & ~3) | (q >> 1);
        const int src2 = src0 + 2;
        #pragma unroll
        for (int ks = 0; ks < 8; ++ks) {
            float v00 = __shfl_sync(0xffffffffu, s[ks][0], src0);
            float v01 = __shfl_sync(0xffffffffu, s[ks][1], src0);
            float v20 = __shfl_sync(0xffffffffu, s[ks][2], src0);
            float v21 = __shfl_sync(0xffffffffu, s[ks][3], src0);
            float w00 = __shfl_sync(0xffffffffu, s[ks][0], src2);
            float w01 = __shfl_sync(0xffffffffu, s[ks][1], src2);
            float w20 = __shfl_sync(0xffffffffu, s[ks][2], src2);
            float w21 = __shfl_sync(0xffffffffu, s[ks][3], src2);
            uint32_t a0 = __float_as_uint((q & 1) ? v01 : v00);
            uint32_t a1 = __float_as_uint((q & 1) ? v21 : v20);
            uint32_t a2 = __float_as_uint((q & 1) ? w01 : w00);
            uint32_t a3 = __float_as_uint((q & 1) ? w21 : w20);
            #pragma unroll
            for (int nt = 0; nt < 8; ++nt) {
                uint32_t b0 = V0[(ks * 8 + q) * VPAD + nt * 8 + g];
                uint32_t b1 = V0[(ks * 8 + q + 4) * VPAD + nt * 8 + g];
                mma_tf32(o[nt], a0, a1, a2, a3, b0, b1);
            }
        }
        __syncthreads();
    }

    // Normalize + write ctx (tf32-rounded for oproj)
    const float invA = 1.0f / lA, invB = 1.0f / lB;
    const int b = bh >> 4, h = bh & 15;
    float* base0 = g_ctx + ((size_t)(b * S_) + mrow0) * DOUT + h * HD_;
    float* base1 = base0 + (size_t)8 * DOUT;
    #pragma unroll
    for (int nt = 0; nt < 8; ++nt) {
        int col = nt * 8 + 2 * q;
        float2 v0 = {rtf(o[nt][0] * invA), rtf(o[nt][1] * invA)};
        float2 v1 = {rtf(o[nt][2] * invB), rtf(o[nt][3] * invB)};
        *reinterpret_cast<float2*>(base0 + col) = v0;
        *reinterpret_cast<float2*>(base1 + col) = v1;
    }
}

// ---------------------------------------------------------------------------
extern "C" void kernel_launch(void* const* d_in, const int* in_sizes, int n_in,
                              void* d_out, int out_size)
{
    const float* x  = (const float*)d_in[0];
    const float* Wq = (const float*)d_in[1];
    const float* Wk = (const float*)d_in[2];
    const float* Wv = (const float*)d_in[3];
    const float* Wo = (const float*)d_in[4];
    const float* bo = (const float*)d_in[5];
    float* out = (float*)d_out;

    const int gemm_smem  = 4 * GSTGW * 4;                 // 73728 B
    const int flash_smem = (2 * KSTGW + 2 * VSTGW) * 4;   // 71680 B
    cudaFuncSetAttribute(qkv_tc_kernel,
        cudaFuncAttributeMaxDynamicSharedMemorySize, gemm_smem);
    cudaFuncSetAttribute(oproj_tc_kernel,
        cudaFuncAttributeMaxDynamicSharedMemorySize, gemm_smem);
    cudaFuncSetAttribute(flash_tc_kernel,
        cudaFuncAttributeMaxDynamicSharedMemorySize, flash_smem);

    const int nCvt = (XF4 + DOUT * DOUT / 4 + 255) / 256;
    cvt_pre_kernel<<<nCvt, 256>>>(x, Wo);
    transpose3_kernel<<<dim3(32, 32, 3), dim3(32, 8)>>>(Wq, Wk, Wv);
    qkv_tc_kernel<<<dim3(64, 24), 256, gemm_smem>>>();
    flash_tc_kernel<<<dim3(16, 64), 256, flash_smem>>>();
    oproj_tc_kernel<<<dim3(64, 8), 256, gemm_smem>>>(bo, out);
}

// round 5
// speedup vs baseline: 7.2833x; 1.0456x over previous
#include <cuda_runtime.h>
#include <cstdint>

#define B_   4
#define S_   2048
#define DIN  1024
#define DOUT 1024
#define H_   16
#define HD_  64
#define KDIM 1024

// ---------------------------------------------------------------------------
// Scratch (module-scope device arrays: allowed; no runtime allocation)
// ---------------------------------------------------------------------------
__device__ float g_Q[B_ * H_ * S_ * HD_];    // (b,h,s,hd)   tf32-rounded
__device__ float g_K[B_ * H_ * S_ * HD_];
__device__ float g_V[B_ * H_ * S_ * HD_];
__device__ float g_ctx[B_ * S_ * DOUT];      // (b,s,d)      tf32-rounded
__device__ float g_WT[3 * DIN * DOUT];       // Wq^T,Wk^T,Wv^T [n][k] tf32-rounded
__device__ float g_X [B_ * S_ * DIN];        // x, tf32-rounded
__device__ float g_Wo[DOUT * DOUT];          // Wo, tf32-rounded

// ---------------------------------------------------------------------------
// helpers
// ---------------------------------------------------------------------------
__device__ __forceinline__ uint32_t f2tf32(float f) {
    uint32_t r;
    asm("cvt.rna.tf32.f32 %0, %1;" : "=r"(r) : "f"(f));
    return r;
}
__device__ __forceinline__ float rtf(float f) { return __uint_as_float(f2tf32(f)); }

__device__ __forceinline__ uint32_t smem_u32(const void* p) {
    uint32_t a;
    asm("{ .reg .u64 t; cvta.to.shared.u64 t, %1; cvt.u32.u64 %0, t; }"
        : "=r"(a) : "l"(p));
    return a;
}
__device__ __forceinline__ void cp16(uint32_t dst, const void* src) {
    asm volatile("cp.async.cg.shared.global [%0], [%1], 16;"
                 :: "r"(dst), "l"(src) : "memory");
}
#define CP_COMMIT() asm volatile("cp.async.commit_group;" ::: "memory")
#define CP_WAIT(n)  asm volatile("cp.async.wait_group %0;" :: "n"(n) : "memory")

// D += A*B, m16n8k8 tf32 (fp32 accumulate)
__device__ __forceinline__ void mma_tf32(float* d,
    uint32_t a0, uint32_t a1, uint32_t a2, uint32_t a3,
    uint32_t b0, uint32_t b1)
{
    asm volatile(
        "mma.sync.aligned.m16n8k8.row.col.f32.tf32.tf32.f32 "
        "{%0,%1,%2,%3}, {%4,%5,%6,%7}, {%8,%9}, {%0,%1,%2,%3};"
        : "+f"(d[0]), "+f"(d[1]), "+f"(d[2]), "+f"(d[3])
        : "r"(a0), "r"(a1), "r"(a2), "r"(a3), "r"(b0), "r"(b1));
}

// ---------------------------------------------------------------------------
// Kernel P: pre-round x -> g_X and Wo -> g_Wo (tf32 rna)
// ---------------------------------------------------------------------------
#define XF4 (B_ * S_ * DIN / 4)
__global__ __launch_bounds__(256) void cvt_pre_kernel(
    const float* __restrict__ x, const float* __restrict__ Wo)
{
    int i = blockIdx.x * 256 + threadIdx.x;
    if (i < XF4) {
        float4 v = *reinterpret_cast<const float4*>(x + (size_t)i * 4);
        float4 r = {rtf(v.x), rtf(v.y), rtf(v.z), rtf(v.w)};
        *reinterpret_cast<float4*>(g_X + (size_t)i * 4) = r;
    } else {
        int j = i - XF4;
        float4 v = *reinterpret_cast<const float4*>(Wo + (size_t)j * 4);
        float4 r = {rtf(v.x), rtf(v.y), rtf(v.z), rtf(v.w)};
        *reinterpret_cast<float4*>(g_Wo + (size_t)j * 4) = r;
    }
}

// ---------------------------------------------------------------------------
// Kernel 0: transpose Wq/Wk/Wv ([K,N] -> [N,K]) + tf32 round, into g_WT
// ---------------------------------------------------------------------------
__global__ __launch_bounds__(256) void transpose3_kernel(
    const float* __restrict__ Wq,
    const float* __restrict__ Wk,
    const float* __restrict__ Wv)
{
    __shared__ float t[32][33];
    const float* src = (blockIdx.z == 0) ? Wq : (blockIdx.z == 1) ? Wk : Wv;
    float* dst = g_WT + (size_t)blockIdx.z * DIN * DOUT;
    const int bx = blockIdx.x * 32, by = blockIdx.y * 32;
    const int tx = threadIdx.x, ty = threadIdx.y;
    #pragma unroll
    for (int i = 0; i < 32; i += 8)
        t[ty + i][tx] = src[(size_t)(by + ty + i) * DOUT + bx + tx];
    __syncthreads();
    #pragma unroll
    for (int i = 0; i < 32; i += 8)
        dst[(size_t)(bx + ty + i) * DIN + by + tx] = rtf(t[tx][ty + i]);
}

// ---------------------------------------------------------------------------
// GEMM via mma.sync tf32: C[128x128] = A[128xK] * B[128xK]^T
// 256 threads, 8 warps (2m x 4n), warp tile 64x32, BK=32, double buffered.
// ---------------------------------------------------------------------------
#define GPAD  36
#define GSTGW (128 * GPAD)
#define GSTGB (GSTGW * 4)
#define NCH32 (KDIM / 32)

#define GEMM_ISSUE(ch, stage) do {                                          \
    _Pragma("unroll")                                                       \
    for (int i_ = 0; i_ < 4; ++i_) {                                        \
        int f_ = tid + i_ * 256, row_ = f_ >> 3, k4_ = f_ & 7;              \
        uint32_t off_ = (uint32_t)(stage) * GSTGB +                         \
                        (uint32_t)(row_ * GPAD + k4_ * 4) * 4u;             \
        cp16(uA + off_, Asrc + (size_t)row_ * KDIM + (ch) * 32 + k4_ * 4);  \
        cp16(uB + off_, Bsrc + (size_t)row_ * KDIM + (ch) * 32 + k4_ * 4);  \
    }                                                                       \
    CP_COMMIT();                                                            \
} while (0)

__device__ __forceinline__ void gemm_tc_mainloop(
    const float* __restrict__ Asrc, const float* __restrict__ Bsrc,
    uint32_t* As, uint32_t* Bs, float acc[4][4][4],
    int tid, int wm, int wn, int g, int q)
{
    #pragma unroll
    for (int mt = 0; mt < 4; ++mt)
        #pragma unroll
        for (int nt = 0; nt < 4; ++nt)
            #pragma unroll
            for (int j = 0; j < 4; ++j) acc[mt][nt][j] = 0.0f;

    const uint32_t uA = smem_u32(As), uB = smem_u32(Bs);

    GEMM_ISSUE(0, 0);
    for (int ch = 0; ch < NCH32; ++ch) {
        const int cur = ch & 1;
        if (ch + 1 < NCH32) { GEMM_ISSUE(ch + 1, cur ^ 1); CP_WAIT(1); }
        else                { CP_WAIT(0); }
        __syncthreads();

        const uint32_t* A0 = As + cur * GSTGW;
        const uint32_t* B0 = Bs + cur * GSTGW;
        #pragma unroll
        for (int ks = 0; ks < 4; ++ks) {
            uint32_t a[4][4], b[4][2];
            #pragma unroll
            for (int mt = 0; mt < 4; ++mt) {
                int m0 = wm * 64 + mt * 16 + g;
                a[mt][0] = A0[m0 * GPAD + ks * 8 + q];
                a[mt][1] = A0[(m0 + 8) * GPAD + ks * 8 + q];
                a[mt][2] = A0[m0 * GPAD + ks * 8 + q + 4];
                a[mt][3] = A0[(m0 + 8) * GPAD + ks * 8 + q + 4];
            }
            #pragma unroll
            for (int nt = 0; nt < 4; ++nt) {
                int n0 = wn * 32 + nt * 8 + g;
                b[nt][0] = B0[n0 * GPAD + ks * 8 + q];
                b[nt][1] = B0[n0 * GPAD + ks * 8 + q + 4];
            }
            #pragma unroll
            for (int mt = 0; mt < 4; ++mt)
                #pragma unroll
                for (int nt = 0; nt < 4; ++nt)
                    mma_tf32(acc[mt][nt], a[mt][0], a[mt][1], a[mt][2], a[mt][3],
                             b[nt][0], b[nt][1]);
        }
        __syncthreads();
    }
}

// ---------------------------------------------------------------------------
// Kernel 1: QKV projection.  grid (64, 24), 256 threads, dyn smem.
// ---------------------------------------------------------------------------
__global__ __launch_bounds__(256, 2) void qkv_tc_kernel()
{
    extern __shared__ uint32_t dyn[];
    uint32_t* As = dyn;
    uint32_t* Bs = dyn + 2 * GSTGW;

    const int tid = threadIdx.x;
    const int wid = tid >> 5, lane = tid & 31;
    const int g = lane >> 2, q = lane & 3;
    const int wm = wid >> 2, wn = wid & 3;

    const int rowBase = blockIdx.x * 128;
    const int n0glob  = blockIdx.y * 128;
    const int w       = n0glob >> 10;
    const int nw      = n0glob & 1023;

    float acc[4][4][4];
    gemm_tc_mainloop(g_X + (size_t)rowBase * KDIM,
                     g_WT + (size_t)n0glob * KDIM,
                     As, Bs, acc, tid, wm, wn, g, q);

    float* obuf = (w == 0) ? g_Q : (w == 1) ? g_K : g_V;
    #pragma unroll
    for (int mt = 0; mt < 4; ++mt) {
        int m0 = rowBase + wm * 64 + mt * 16 + g;
        int b0 = m0 >> 11, s0 = m0 & 2047;
        int m1 = m0 + 8;
        int b1 = m1 >> 11, s1 = m1 & 2047;
        #pragma unroll
        for (int nt = 0; nt < 4; ++nt) {
            int n  = nw + wn * 32 + nt * 8 + 2 * q;
            int h  = n >> 6, hd = n & 63;
            float2 v0 = {rtf(acc[mt][nt][0]), rtf(acc[mt][nt][1])};
            float2 v1 = {rtf(acc[mt][nt][2]), rtf(acc[mt][nt][3])};
            *reinterpret_cast<float2*>(
                &obuf[(((size_t)(b0 * H_ + h) * S_) + s0) * HD_ + hd]) = v0;
            *reinterpret_cast<float2*>(
                &obuf[(((size_t)(b1 * H_ + h) * S_) + s1) * HD_ + hd]) = v1;
        }
    }
}

// ---------------------------------------------------------------------------
// Kernel 3: output projection.  out = ctx @ Wo^T + bo.  grid (64, 8).
// ---------------------------------------------------------------------------
__global__ __launch_bounds__(256, 2) void oproj_tc_kernel(
    const float* __restrict__ bo, float* __restrict__ out)
{
    extern __shared__ uint32_t dyn[];
    uint32_t* As = dyn;
    uint32_t* Bs = dyn + 2 * GSTGW;

    const int tid = threadIdx.x;
    const int wid = tid >> 5, lane = tid & 31;
    const int g = lane >> 2, q = lane & 3;
    const int wm = wid >> 2, wn = wid & 3;

    const int rowBase = blockIdx.x * 128;
    const int n0      = blockIdx.y * 128;

    float acc[4][4][4];
    gemm_tc_mainloop(g_ctx + (size_t)rowBase * KDIM,
                     g_Wo + (size_t)n0 * KDIM,
                     As, Bs, acc, tid, wm, wn, g, q);

    #pragma unroll
    for (int mt = 0; mt < 4; ++mt) {
        int m0 = rowBase + wm * 64 + mt * 16 + g;
        #pragma unroll
        for (int nt = 0; nt < 4; ++nt) {
            int n = n0 + wn * 32 + nt * 8 + 2 * q;
            float2 bias = *reinterpret_cast<const float2*>(&bo[n]);
            float2 v0 = {acc[mt][nt][0] + bias.x, acc[mt][nt][1] + bias.y};
            float2 v1 = {acc[mt][nt][2] + bias.x, acc[mt][nt][3] + bias.y};
            *reinterpret_cast<float2*>(&out[(size_t)m0 * DOUT + n])       = v0;
            *reinterpret_cast<float2*>(&out[(size_t)(m0 + 8) * DOUT + n]) = v1;
        }
    }
}

// ---------------------------------------------------------------------------
// Kernel 2: causal flash attention via mma.sync tf32, cp.async double buffer.
// 128 queries per block, 8 warps x 16 rows.  grid (16, 64), 256 threads.
// __launch_bounds__(256, 2): cap regs at 128 so 2 CTAs/SM fit the RF.
// ---------------------------------------------------------------------------
#define KPAD 68
#define VPAD 72
#define KSTGW (64 * KPAD)
#define VSTGW (64 * VPAD)

#define FLASH_ISSUE(c, stage) do {                                           \
    const float* Kp_ = g_K + ((size_t)bh * S_ + (c) * 64) * HD_;             \
    const float* Vp_ = g_V + ((size_t)bh * S_ + (c) * 64) * HD_;             \
    _Pragma("unroll")                                                        \
    for (int i_ = 0; i_ < 4; ++i_) {                                         \
        int f_ = tid + i_ * 256, row_ = f_ >> 4, c4_ = f_ & 15;              \
        cp16(uK + (uint32_t)(stage) * (KSTGW * 4) +                          \
                 (uint32_t)(row_ * KPAD + c4_ * 4) * 4u,                     \
             Kp_ + row_ * HD_ + c4_ * 4);                                    \
        cp16(uV + (uint32_t)(stage) * (VSTGW * 4) +                          \
                 (uint32_t)(row_ * VPAD + c4_ * 4) * 4u,                     \
             Vp_ + row_ * HD_ + c4_ * 4);                                    \
    }                                                                        \
    CP_COMMIT();                                                             \
} while (0)

__global__ __launch_bounds__(256, 2) void flash_tc_kernel()
{
    extern __shared__ uint32_t dyn[];
    uint32_t* Ksm = dyn;
    uint32_t* Vsm = dyn + 2 * KSTGW;

    const int tid  = threadIdx.x;
    const int wid  = tid >> 5, lane = tid & 31;
    const int g    = lane >> 2, q = lane & 3;
    const int qt   = (int)gridDim.x - 1 - (int)blockIdx.x;  // big tiles first
    const int bh   = blockIdx.y;
    const int mrow0 = qt * 128 + wid * 16 + g;

    const uint32_t uK = smem_u32(Ksm), uV = smem_u32(Vsm);

    // Q A-fragments (g_Q already tf32-rounded; *0.125 is exact)
    uint32_t qf[8][4];
    {
        const float* Qp = g_Q + ((size_t)bh * S_ + mrow0) * HD_;
        #pragma unroll
        for (int ks = 0; ks < 8; ++ks) {
            qf[ks][0] = __float_as_uint(Qp[ks * 8 + q] * 0.125f);
            qf[ks][1] = __float_as_uint(Qp[8 * HD_ + ks * 8 + q] * 0.125f);
            qf[ks][2] = __float_as_uint(Qp[ks * 8 + q + 4] * 0.125f);
            qf[ks][3] = __float_as_uint(Qp[8 * HD_ + ks * 8 + q + 4] * 0.125f);
        }
    }

    float o[8][4];
    #pragma unroll
    for (int nt = 0; nt < 8; ++nt)
        #pragma unroll
        for (int j = 0; j < 4; ++j) o[nt][j] = 0.0f;
    float mA = -1e30f, mB = -1e30f, lA = 0.0f, lB = 0.0f;

    const int nch = 2 * qt + 2;
    FLASH_ISSUE(0, 0);
    for (int c = 0; c < nch; ++c) {
        const int cur = c & 1;
        if (c + 1 < nch) { FLASH_ISSUE(c + 1, cur ^ 1); CP_WAIT(1); }
        else             { CP_WAIT(0); }
        __syncthreads();

        const uint32_t* K0 = Ksm + cur * KSTGW;
        const uint32_t* V0 = Vsm + cur * VSTGW;

        // S = Q K^T
        float s[8][4];
        #pragma unroll
        for (int nt = 0; nt < 8; ++nt)
            #pragma unroll
            for (int j = 0; j < 4; ++j) s[nt][j] = 0.0f;
        #pragma unroll
        for (int ks = 0; ks < 8; ++ks) {
            #pragma unroll
            for (int nt = 0; nt < 8; ++nt) {
                uint32_t b0 = K0[(nt * 8 + g) * KPAD + ks * 8 + q];
                uint32_t b1 = K0[(nt * 8 + g) * KPAD + ks * 8 + q + 4];
                mma_tf32(s[nt], qf[ks][0], qf[ks][1], qf[ks][2], qf[ks][3], b0, b1);
            }
        }

        if (c >= 2 * qt) {   // causal mask, last two chunks only
            int kb = c * 64;
            #pragma unroll
            for (int nt = 0; nt < 8; ++nt) {
                int col = kb + nt * 8 + 2 * q;
                if (col     > mrow0)     s[nt][0] = -1e30f;
                if (col + 1 > mrow0)     s[nt][1] = -1e30f;
                if (col     > mrow0 + 8) s[nt][2] = -1e30f;
                if (col + 1 > mrow0 + 8) s[nt][3] = -1e30f;
            }
        }

        float tmA = -1e30f, tmB = -1e30f;
        #pragma unroll
        for (int nt = 0; nt < 8; ++nt) {
            tmA = fmaxf(tmA, fmaxf(s[nt][0], s[nt][1]));
            tmB = fmaxf(tmB, fmaxf(s[nt][2], s[nt][3]));
        }
        tmA = fmaxf(tmA, __shfl_xor_sync(0xffffffffu, tmA, 1));
        tmA = fmaxf(tmA, __shfl_xor_sync(0xffffffffu, tmA, 2));
        tmB = fmaxf(tmB, __shfl_xor_sync(0xffffffffu, tmB, 1));
        tmB = fmaxf(tmB, __shfl_xor_sync(0xffffffffu, tmB, 2));
        float mnA = fmaxf(mA, tmA), mnB = fmaxf(mB, tmB);
        float corrA = __expf(mA - mnA), corrB = __expf(mB - mnB);
        lA *= corrA; lB *= corrB;
        #pragma unroll
        for (int nt = 0; nt < 8; ++nt) {
            o[nt][0] *= corrA; o[nt][1] *= corrA;
            o[nt][2] *= corrB; o[nt][3] *= corrB;
        }

        float sumA = 0.0f, sumB = 0.0f;
        #pragma unroll
        for (int nt = 0; nt < 8; ++nt) {
            float p0 = __expf(s[nt][0] - mnA);
            float p1 = __expf(s[nt][1] - mnA);
            float p2 = __expf(s[nt][2] - mnB);
            float p3 = __expf(s[nt][3] - mnB);
            sumA += p0 + p1; sumB += p2 + p3;
            s[nt][0] = __uint_as_float(f2tf32(p0));
            s[nt][1] = __uint_as_float(f2tf32(p1));
            s[nt][2] = __uint_as_float(f2tf32(p2));
            s[nt][3] = __uint_as_float(f2tf32(p3));
        }
        sumA += __shfl_xor_sync(0xffffffffu, sumA, 1);
        sumA += __shfl_xor_sync(0xffffffffu, sumA, 2);
        sumB += __shfl_xor_sync(0xffffffffu, sumB, 1);
        sumB += __shfl_xor_sync(0xffffffffu, sumB, 2);
        lA += sumA; lB += sumB;
        mA = mnA; mB = mnB;

        // O += P V   (P C-frag -> A-frag via shuffles)
        const int src0 = (lane & ~3) | (q >> 1);
        const int src2 = src0 + 2;
        #pragma unroll
        for (int ks = 0; ks < 8; ++ks) {
            float v00 = __shfl_sync(0xffffffffu, s[ks][0], src0);
            float v01 = __shfl_sync(0xffffffffu, s[ks][1], src0);
            float v20 = __shfl_sync(0xffffffffu, s[ks][2], src0);
            float v21 = __shfl_sync(0xffffffffu, s[ks][3], src0);
            float w00 = __shfl_sync(0xffffffffu, s[ks][0], src2);
            float w01 = __shfl_sync(0xffffffffu, s[ks][1], src2);
            float w20 = __shfl_sync(0xffffffffu, s[ks][2], src2);
            float w21 = __shfl_sync(0xffffffffu, s[ks][3], src2);
            uint32_t a0 = __float_as_uint((q & 1) ? v01 : v00);
            uint32_t a1 = __float_as_uint((q & 1) ? v21 : v20);
            uint32_t a2 = __float_as_uint((q & 1) ? w01 : w00);
            uint32_t a3 = __float_as_uint((q & 1) ? w21 : w20);
            #pragma unroll
            for (int nt = 0; nt < 8; ++nt) {
                uint32_t b0 = V0[(ks * 8 + q) * VPAD + nt * 8 + g];
                uint32_t b1 = V0[(ks * 8 + q + 4) * VPAD + nt * 8 + g];
                mma_tf32(o[nt], a0, a1, a2, a3, b0, b1);
            }
        }
        __syncthreads();
    }

    // Normalize + write ctx (tf32-rounded for oproj)
    const float invA = 1.0f / lA, invB = 1.0f / lB;
    const int b = bh >> 4, h = bh & 15;
    float* base0 = g_ctx + ((size_t)(b * S_) + mrow0) * DOUT + h * HD_;
    float* base1 = base0 + (size_t)8 * DOUT;
    #pragma unroll
    for (int nt = 0; nt < 8; ++nt) {
        int col = nt * 8 + 2 * q;
        float2 v0 = {rtf(o[nt][0] * invA), rtf(o[nt][1] * invA)};
        float2 v1 = {rtf(o[nt][2] * invB), rtf(o[nt][3] * invB)};
        *reinterpret_cast<float2*>(base0 + col) = v0;
        *reinterpret_cast<float2*>(base1 + col) = v1;
    }
}

// ---------------------------------------------------------------------------
extern "C" void kernel_launch(void* const* d_in, const int* in_sizes, int n_in,
                              void* d_out, int out_size)
{
    const float* x  = (const float*)d_in[0];
    const float* Wq = (const float*)d_in[1];
    const float* Wk = (const float*)d_in[2];
    const float* Wv = (const float*)d_in[3];
    const float* Wo = (const float*)d_in[4];
    const float* bo = (const float*)d_in[5];
    float* out = (float*)d_out;

    const int gemm_smem  = 4 * GSTGW * 4;                 // 73728 B
    const int flash_smem = (2 * KSTGW + 2 * VSTGW) * 4;   // 71680 B
    cudaFuncSetAttribute(qkv_tc_kernel,
        cudaFuncAttributeMaxDynamicSharedMemorySize, gemm_smem);
    cudaFuncSetAttribute(oproj_tc_kernel,
        cudaFuncAttributeMaxDynamicSharedMemorySize, gemm_smem);
    cudaFuncSetAttribute(flash_tc_kernel,
        cudaFuncAttributeMaxDynamicSharedMemorySize, flash_smem);

    const int nCvt = (XF4 + DOUT * DOUT / 4 + 255) / 256;
    cvt_pre_kernel<<<nCvt, 256>>>(x, Wo);
    transpose3_kernel<<<dim3(32, 32, 3), dim3(32, 8)>>>(Wq, Wk, Wv);
    qkv_tc_kernel<<<dim3(64, 24), 256, gemm_smem>>>();
    flash_tc_kernel<<<dim3(16, 64), 256, flash_smem>>>();
    oproj_tc_kernel<<<dim3(64, 8), 256, gemm_smem>>>(bo, out);
}

// round 6
// speedup vs baseline: 7.9187x; 1.0872x over previous
#include <cuda_runtime.h>
#include <cstdint>

#define B_   4
#define S_   2048
#define DIN  1024
#define DOUT 1024
#define H_   16
#define HD_  64
#define KDIM 1024

// ---------------------------------------------------------------------------
// Scratch (module-scope device arrays: allowed; no runtime allocation)
// ---------------------------------------------------------------------------
__device__ float g_Q[B_ * H_ * S_ * HD_];    // (b,h,s,hd)    tf32-rounded
__device__ float g_K[B_ * H_ * S_ * HD_];    // (b,h,s,hd)    tf32-rounded
__device__ float g_V[B_ * H_ * S_ * HD_];    // (b,h,hd,s)    TRANSPOSED, tf32-rounded
__device__ float g_ctx[B_ * S_ * DOUT];      // (b,s,d)       tf32-rounded
__device__ float g_WT[3 * DIN * DOUT];       // Wq^T,Wk^T,Wv^T [n][k] tf32-rounded
__device__ float g_X [B_ * S_ * DIN];        // x, tf32-rounded
__device__ float g_Wo[DOUT * DOUT];          // Wo, tf32-rounded

// ---------------------------------------------------------------------------
// helpers
// ---------------------------------------------------------------------------
__device__ __forceinline__ uint32_t f2tf32(float f) {
    uint32_t r;
    asm("cvt.rna.tf32.f32 %0, %1;" : "=r"(r) : "f"(f));
    return r;
}
__device__ __forceinline__ float rtf(float f) { return __uint_as_float(f2tf32(f)); }

__device__ __forceinline__ float fexp2(float x) {
    float y;
    asm("ex2.approx.f32 %0, %1;" : "=f"(y) : "f"(x));
    return y;
}

__device__ __forceinline__ uint32_t smem_u32(const void* p) {
    uint32_t a;
    asm("{ .reg .u64 t; cvta.to.shared.u64 t, %1; cvt.u32.u64 %0, t; }"
        : "=r"(a) : "l"(p));
    return a;
}
__device__ __forceinline__ void cp16(uint32_t dst, const void* src) {
    asm volatile("cp.async.cg.shared.global [%0], [%1], 16;"
                 :: "r"(dst), "l"(src) : "memory");
}
#define CP_COMMIT() asm volatile("cp.async.commit_group;" ::: "memory")
#define CP_WAIT(n)  asm volatile("cp.async.wait_group %0;" :: "n"(n) : "memory")

__device__ __forceinline__ void ldsm_x4(uint32_t addr,
    uint32_t& r0, uint32_t& r1, uint32_t& r2, uint32_t& r3)
{
    asm volatile("ldmatrix.sync.aligned.m8n8.x4.shared.b16 {%0,%1,%2,%3}, [%4];"
        : "=r"(r0), "=r"(r1), "=r"(r2), "=r"(r3) : "r"(addr));
}

// D += A*B, m16n8k8 tf32 (fp32 accumulate)
__device__ __forceinline__ void mma_tf32(float* d,
    uint32_t a0, uint32_t a1, uint32_t a2, uint32_t a3,
    uint32_t b0, uint32_t b1)
{
    asm volatile(
        "mma.sync.aligned.m16n8k8.row.col.f32.tf32.tf32.f32 "
        "{%0,%1,%2,%3}, {%4,%5,%6,%7}, {%8,%9}, {%0,%1,%2,%3};"
        : "+f"(d[0]), "+f"(d[1]), "+f"(d[2]), "+f"(d[3])
        : "r"(a0), "r"(a1), "r"(a2), "r"(a3), "r"(b0), "r"(b1));
}

// ---------------------------------------------------------------------------
// Kernel P: pre-round x -> g_X and Wo -> g_Wo (tf32 rna)
// ---------------------------------------------------------------------------
#define XF4 (B_ * S_ * DIN / 4)
__global__ __launch_bounds__(256) void cvt_pre_kernel(
    const float* __restrict__ x, const float* __restrict__ Wo)
{
    int i = blockIdx.x * 256 + threadIdx.x;
    if (i < XF4) {
        float4 v = *reinterpret_cast<const float4*>(x + (size_t)i * 4);
        float4 r = {rtf(v.x), rtf(v.y), rtf(v.z), rtf(v.w)};
        *reinterpret_cast<float4*>(g_X + (size_t)i * 4) = r;
    } else {
        int j = i - XF4;
        float4 v = *reinterpret_cast<const float4*>(Wo + (size_t)j * 4);
        float4 r = {rtf(v.x), rtf(v.y), rtf(v.z), rtf(v.w)};
        *reinterpret_cast<float4*>(g_Wo + (size_t)j * 4) = r;
    }
}

// ---------------------------------------------------------------------------
// Kernel 0: transpose Wq/Wk/Wv ([K,N] -> [N,K]) + tf32 round, into g_WT
// ---------------------------------------------------------------------------
__global__ __launch_bounds__(256) void transpose3_kernel(
    const float* __restrict__ Wq,
    const float* __restrict__ Wk,
    const float* __restrict__ Wv)
{
    __shared__ float t[32][33];
    const float* src = (blockIdx.z == 0) ? Wq : (blockIdx.z == 1) ? Wk : Wv;
    float* dst = g_WT + (size_t)blockIdx.z * DIN * DOUT;
    const int bx = blockIdx.x * 32, by = blockIdx.y * 32;
    const int tx = threadIdx.x, ty = threadIdx.y;
    #pragma unroll
    for (int i = 0; i < 32; i += 8)
        t[ty + i][tx] = src[(size_t)(by + ty + i) * DOUT + bx + tx];
    __syncthreads();
    #pragma unroll
    for (int i = 0; i < 32; i += 8)
        dst[(size_t)(bx + ty + i) * DIN + by + tx] = rtf(t[tx][ty + i]);
}

// ---------------------------------------------------------------------------
// GEMM via mma.sync tf32: C[128x128] = A[128xK] * B[128xK]^T
// 256 threads, 8 warps (2m x 4n), warp tile 64x32, BK=32, double buffered.
// Fragment loads via ldmatrix.x4.
// ---------------------------------------------------------------------------
#define GPAD  36
#define GSTGW (128 * GPAD)
#define GSTGB (GSTGW * 4)
#define NCH32 (KDIM / 32)

#define GEMM_ISSUE(ch, stage) do {                                          \
    _Pragma("unroll")                                                       \
    for (int i_ = 0; i_ < 4; ++i_) {                                        \
        int f_ = tid + i_ * 256, row_ = f_ >> 3, k4_ = f_ & 7;              \
        uint32_t off_ = (uint32_t)(stage) * GSTGB +                         \
                        (uint32_t)(row_ * GPAD + k4_ * 4) * 4u;             \
        cp16(uA + off_, Asrc + (size_t)row_ * KDIM + (ch) * 32 + k4_ * 4);  \
        cp16(uB + off_, Bsrc + (size_t)row_ * KDIM + (ch) * 32 + k4_ * 4);  \
    }                                                                       \
    CP_COMMIT();                                                            \
} while (0)

__device__ __forceinline__ void gemm_tc_mainloop(
    const float* __restrict__ Asrc, const float* __restrict__ Bsrc,
    uint32_t* As, uint32_t* Bs, float acc[4][4][4],
    int tid, int wm, int wn)
{
    const int lane = tid & 31;
    #pragma unroll
    for (int mt = 0; mt < 4; ++mt)
        #pragma unroll
        for (int nt = 0; nt < 4; ++nt)
            #pragma unroll
            for (int j = 0; j < 4; ++j) acc[mt][nt][j] = 0.0f;

    const uint32_t uA = smem_u32(As), uB = smem_u32(Bs);

    // ldmatrix per-lane addressing
    const int rowA = lane & 15;                          // A: rows m0+0..15
    const int csA  = (lane >> 4) << 2;                   //    k cols 0 / +4
    const int rowB = ((lane >> 4) << 3) + (lane & 7);    // B: rows n0+0..15
    const int csB  = ((lane >> 3) & 1) << 2;             //    k cols 0 / +4
    const uint32_t baseA = uA + (uint32_t)((wm * 64 + rowA) * GPAD + csA) * 4u;
    const uint32_t baseB = uB + (uint32_t)((wn * 32 + rowB) * GPAD + csB) * 4u;

    GEMM_ISSUE(0, 0);
    for (int ch = 0; ch < NCH32; ++ch) {
        const int cur = ch & 1;
        if (ch + 1 < NCH32) { GEMM_ISSUE(ch + 1, cur ^ 1); CP_WAIT(1); }
        else                { CP_WAIT(0); }
        __syncthreads();

        const uint32_t stg = (uint32_t)cur * GSTGB;
        #pragma unroll
        for (int ks = 0; ks < 4; ++ks) {
            uint32_t a[4][4], b[4][2];
            #pragma unroll
            for (int mt = 0; mt < 4; ++mt)
                ldsm_x4(baseA + stg + (uint32_t)(mt * 16 * GPAD + ks * 8) * 4u,
                        a[mt][0], a[mt][1], a[mt][2], a[mt][3]);
            #pragma unroll
            for (int ntp = 0; ntp < 2; ++ntp)
                ldsm_x4(baseB + stg + (uint32_t)(ntp * 16 * GPAD + ks * 8) * 4u,
                        b[2 * ntp][0], b[2 * ntp][1],
                        b[2 * ntp + 1][0], b[2 * ntp + 1][1]);
            #pragma unroll
            for (int mt = 0; mt < 4; ++mt)
                #pragma unroll
                for (int nt = 0; nt < 4; ++nt)
                    mma_tf32(acc[mt][nt], a[mt][0], a[mt][1], a[mt][2], a[mt][3],
                             b[nt][0], b[nt][1]);
        }
        __syncthreads();
    }
}

// ---------------------------------------------------------------------------
// Kernel 1: QKV projection.  grid (64, 24), 256 threads, dyn smem.
// Q/K written (b,h,s,hd); V written TRANSPOSED (b,h,hd,s).
// ---------------------------------------------------------------------------
__global__ __launch_bounds__(256, 2) void qkv_tc_kernel()
{
    extern __shared__ uint32_t dyn[];
    uint32_t* As = dyn;
    uint32_t* Bs = dyn + 2 * GSTGW;

    const int tid = threadIdx.x;
    const int wid = tid >> 5, lane = tid & 31;
    const int g = lane >> 2, q = lane & 3;
    const int wm = wid >> 2, wn = wid & 3;

    const int rowBase = blockIdx.x * 128;
    const int n0glob  = blockIdx.y * 128;
    const int w       = n0glob >> 10;
    const int nw      = n0glob & 1023;

    float acc[4][4][4];
    gemm_tc_mainloop(g_X + (size_t)rowBase * KDIM,
                     g_WT + (size_t)n0glob * KDIM,
                     As, Bs, acc, tid, wm, wn);

    if (w == 2) {
        // V: transposed scatter (b,h,hd,s)
        #pragma unroll
        for (int mt = 0; mt < 4; ++mt) {
            int m0 = rowBase + wm * 64 + mt * 16 + g;
            int b0 = m0 >> 11, s0 = m0 & 2047;
            int m1 = m0 + 8;
            int b1 = m1 >> 11, s1 = m1 & 2047;
            #pragma unroll
            for (int nt = 0; nt < 4; ++nt) {
                int n  = nw + wn * 32 + nt * 8 + 2 * q;
                int h  = n >> 6, hd = n & 63;
                float* v0 = &g_V[(((size_t)(b0 * H_ + h) * HD_) + hd) * S_ + s0];
                float* v1 = &g_V[(((size_t)(b1 * H_ + h) * HD_) + hd) * S_ + s1];
                v0[0]  = rtf(acc[mt][nt][0]);
                v0[S_] = rtf(acc[mt][nt][1]);
                v1[0]  = rtf(acc[mt][nt][2]);
                v1[S_] = rtf(acc[mt][nt][3]);
            }
        }
    } else {
        float* obuf = (w == 0) ? g_Q : g_K;
        #pragma unroll
        for (int mt = 0; mt < 4; ++mt) {
            int m0 = rowBase + wm * 64 + mt * 16 + g;
            int b0 = m0 >> 11, s0 = m0 & 2047;
            int m1 = m0 + 8;
            int b1 = m1 >> 11, s1 = m1 & 2047;
            #pragma unroll
            for (int nt = 0; nt < 4; ++nt) {
                int n  = nw + wn * 32 + nt * 8 + 2 * q;
                int h  = n >> 6, hd = n & 63;
                float2 v0 = {rtf(acc[mt][nt][0]), rtf(acc[mt][nt][1])};
                float2 v1 = {rtf(acc[mt][nt][2]), rtf(acc[mt][nt][3])};
                *reinterpret_cast<float2*>(
                    &obuf[(((size_t)(b0 * H_ + h) * S_) + s0) * HD_ + hd]) = v0;
                *reinterpret_cast<float2*>(
                    &obuf[(((size_t)(b1 * H_ + h) * S_) + s1) * HD_ + hd]) = v1;
            }
        }
    }
}

// ---------------------------------------------------------------------------
// Kernel 3: output projection.  out = ctx @ Wo^T + bo.  grid (64, 8).
// ---------------------------------------------------------------------------
__global__ __launch_bounds__(256, 2) void oproj_tc_kernel(
    const float* __restrict__ bo, float* __restrict__ out)
{
    extern __shared__ uint32_t dyn[];
    uint32_t* As = dyn;
    uint32_t* Bs = dyn + 2 * GSTGW;

    const int tid = threadIdx.x;
    const int wid = tid >> 5, lane = tid & 31;
    const int g = lane >> 2, q = lane & 3;
    const int wm = wid >> 2, wn = wid & 3;

    const int rowBase = blockIdx.x * 128;
    const int n0      = blockIdx.y * 128;

    float acc[4][4][4];
    gemm_tc_mainloop(g_ctx + (size_t)rowBase * KDIM,
                     g_Wo + (size_t)n0 * KDIM,
                     As, Bs, acc, tid, wm, wn);

    #pragma unroll
    for (int mt = 0; mt < 4; ++mt) {
        int m0 = rowBase + wm * 64 + mt * 16 + g;
        #pragma unroll
        for (int nt = 0; nt < 4; ++nt) {
            int n = n0 + wn * 32 + nt * 8 + 2 * q;
            float2 bias = *reinterpret_cast<const float2*>(&bo[n]);
            float2 v0 = {acc[mt][nt][0] + bias.x, acc[mt][nt][1] + bias.y};
            float2 v1 = {acc[mt][nt][2] + bias.x, acc[mt][nt][3] + bias.y};
            *reinterpret_cast<float2*>(&out[(size_t)m0 * DOUT + n])       = v0;
            *reinterpret_cast<float2*>(&out[(size_t)(m0 + 8) * DOUT + n]) = v1;
        }
    }
}

// ---------------------------------------------------------------------------
// Kernel 2: causal flash attention via mma.sync tf32 + ldmatrix + cp.async.
// 128 queries per block, 8 warps x 16 rows.  grid (16, 64), 256 threads.
// Softmax in exp2 domain (Q pre-scaled by 0.125*log2(e)).
// K staged [key][hd] (pad 68); V staged [hd][key] from transposed g_V (pad 68).
// ---------------------------------------------------------------------------
#define KPAD  68
#define KSTGW (64 * KPAD)
#define KSTGB (KSTGW * 4)

#define FLASH_ISSUE(c, stage) do {                                           \
    const float* Kp_ = g_K + ((size_t)bh * S_ + (c) * 64) * HD_;             \
    const float* Vp_ = g_V + (size_t)bh * (HD_ * S_) + (c) * 64;             \
    _Pragma("unroll")                                                        \
    for (int i_ = 0; i_ < 4; ++i_) {                                         \
        int f_ = tid + i_ * 256, row_ = f_ >> 4, c4_ = f_ & 15;              \
        uint32_t soff_ = (uint32_t)(stage) * KSTGB +                         \
                         (uint32_t)(row_ * KPAD + c4_ * 4) * 4u;             \
        cp16(uK + soff_, Kp_ + row_ * HD_ + c4_ * 4);                        \
        cp16(uV + soff_, Vp_ + (size_t)row_ * S_ + c4_ * 4);                 \
    }                                                                        \
    CP_COMMIT();                                                             \
} while (0)

__global__ __launch_bounds__(256, 2) void flash_tc_kernel()
{
    extern __shared__ uint32_t dyn[];
    uint32_t* Ksm = dyn;
    uint32_t* Vsm = dyn + 2 * KSTGW;

    const int tid  = threadIdx.x;
    const int wid  = tid >> 5, lane = tid & 31;
    const int g    = lane >> 2, q = lane & 3;
    const int qt   = (int)gridDim.x - 1 - (int)blockIdx.x;  // big tiles first
    const int bh   = blockIdx.y;
    const int mrow0 = qt * 128 + wid * 16 + g;

    const uint32_t uK = smem_u32(Ksm), uV = smem_u32(Vsm);

    // ldmatrix B-fragment addressing (shared by K and V stages)
    const int rowB = ((lane >> 4) << 3) + (lane & 7);
    const int csB  = ((lane >> 3) & 1) << 2;
    const uint32_t baseK = uK + (uint32_t)(rowB * KPAD + csB) * 4u;
    const uint32_t baseV = uV + (uint32_t)(rowB * KPAD + csB) * 4u;

    // Q A-fragments, pre-scaled by 0.125 * log2(e), re-rounded to tf32
    const float QS = 0.125f * 1.4426950408889634f;
    uint32_t qf[8][4];
    {
        const float* Qp = g_Q + ((size_t)bh * S_ + mrow0) * HD_;
        #pragma unroll
        for (int ks = 0; ks < 8; ++ks) {
            qf[ks][0] = f2tf32(Qp[ks * 8 + q] * QS);
            qf[ks][1] = f2tf32(Qp[8 * HD_ + ks * 8 + q] * QS);
            qf[ks][2] = f2tf32(Qp[ks * 8 + q + 4] * QS);
            qf[ks][3] = f2tf32(Qp[8 * HD_ + ks * 8 + q + 4] * QS);
        }
    }

    float o[8][4];
    #pragma unroll
    for (int nt = 0; nt < 8; ++nt)
        #pragma unroll
        for (int j = 0; j < 4; ++j) o[nt][j] = 0.0f;
    float mA = -1e30f, mB = -1e30f, lA = 0.0f, lB = 0.0f;

    const int nch = 2 * qt + 2;
    FLASH_ISSUE(0, 0);
    for (int c = 0; c < nch; ++c) {
        const int cur = c & 1;
        if (c + 1 < nch) { FLASH_ISSUE(c + 1, cur ^ 1); CP_WAIT(1); }
        else             { CP_WAIT(0); }
        __syncthreads();

        const uint32_t stg = (uint32_t)cur * KSTGB;

        // S = Q K^T  (scores in log2 units)
        float s[8][4];
        #pragma unroll
        for (int nt = 0; nt < 8; ++nt)
            #pragma unroll
            for (int j = 0; j < 4; ++j) s[nt][j] = 0.0f;
        #pragma unroll
        for (int ks = 0; ks < 8; ++ks) {
            #pragma unroll
            for (int ntp = 0; ntp < 4; ++ntp) {
                uint32_t b00, b01, b10, b11;
                ldsm_x4(baseK + stg + (uint32_t)(ntp * 16 * KPAD + ks * 8) * 4u,
                        b00, b01, b10, b11);
                mma_tf32(s[2 * ntp],     qf[ks][0], qf[ks][1], qf[ks][2], qf[ks][3], b00, b01);
                mma_tf32(s[2 * ntp + 1], qf[ks][0], qf[ks][1], qf[ks][2], qf[ks][3], b10, b11);
            }
        }

        if (c >= 2 * qt) {   // causal mask, last two chunks only
            int kb = c * 64;
            #pragma unroll
            for (int nt = 0; nt < 8; ++nt) {
                int col = kb + nt * 8 + 2 * q;
                if (col     > mrow0)     s[nt][0] = -1e30f;
                if (col + 1 > mrow0)     s[nt][1] = -1e30f;
                if (col     > mrow0 + 8) s[nt][2] = -1e30f;
                if (col + 1 > mrow0 + 8) s[nt][3] = -1e30f;
            }
        }

        float tmA = -1e30f, tmB = -1e30f;
        #pragma unroll
        for (int nt = 0; nt < 8; ++nt) {
            tmA = fmaxf(tmA, fmaxf(s[nt][0], s[nt][1]));
            tmB = fmaxf(tmB, fmaxf(s[nt][2], s[nt][3]));
        }
        tmA = fmaxf(tmA, __shfl_xor_sync(0xffffffffu, tmA, 1));
        tmA = fmaxf(tmA, __shfl_xor_sync(0xffffffffu, tmA, 2));
        tmB = fmaxf(tmB, __shfl_xor_sync(0xffffffffu, tmB, 1));
        tmB = fmaxf(tmB, __shfl_xor_sync(0xffffffffu, tmB, 2));
        float mnA = fmaxf(mA, tmA), mnB = fmaxf(mB, tmB);
        float corrA = fexp2(mA - mnA), corrB = fexp2(mB - mnB);
        lA *= corrA; lB *= corrB;
        #pragma unroll
        for (int nt = 0; nt < 8; ++nt) {
            o[nt][0] *= corrA; o[nt][1] *= corrA;
            o[nt][2] *= corrB; o[nt][3] *= corrB;
        }

        float sumA = 0.0f, sumB = 0.0f;
        #pragma unroll
        for (int nt = 0; nt < 8; ++nt) {
            float p0 = fexp2(s[nt][0] - mnA);
            float p1 = fexp2(s[nt][1] - mnA);
            float p2 = fexp2(s[nt][2] - mnB);
            float p3 = fexp2(s[nt][3] - mnB);
            sumA += p0 + p1; sumB += p2 + p3;
            s[nt][0] = __uint_as_float(f2tf32(p0));
            s[nt][1] = __uint_as_float(f2tf32(p1));
            s[nt][2] = __uint_as_float(f2tf32(p2));
            s[nt][3] = __uint_as_float(f2tf32(p3));
        }
        sumA += __shfl_xor_sync(0xffffffffu, sumA, 1);
        sumA += __shfl_xor_sync(0xffffffffu, sumA, 2);
        sumB += __shfl_xor_sync(0xffffffffu, sumB, 1);
        sumB += __shfl_xor_sync(0xffffffffu, sumB, 2);
        lA += sumA; lB += sumB;
        mA = mnA; mB = mnB;

        // O += P V   (P C-frag -> A-frag via shuffles; V frags via ldmatrix)
        const int src0 = (lane & ~3) | (q >> 1);
        const int src2 = src0 + 2;
        #pragma unroll
        for (int ks = 0; ks < 8; ++ks) {
            float v00 = __shfl_sync(0xffffffffu, s[ks][0], src0);
            float v01 = __shfl_sync(0xffffffffu, s[ks][1], src0);
            float v20 = __shfl_sync(0xffffffffu, s[ks][2], src0);
            float v21 = __shfl_sync(0xffffffffu, s[ks][3], src0);
            float w00 = __shfl_sync(0xffffffffu, s[ks][0], src2);
            float w01 = __shfl_sync(0xffffffffu, s[ks][1], src2);
            float w20 = __shfl_sync(0xffffffffu, s[ks][2], src2);
            float w21 = __shfl_sync(0xffffffffu, s[ks][3], src2);
            uint32_t a0 = __float_as_uint((q & 1) ? v01 : v00);
            uint32_t a1 = __float_as_uint((q & 1) ? v21 : v20);
            uint32_t a2 = __float_as_uint((q & 1) ? w01 : w00);
            uint32_t a3 = __float_as_uint((q & 1) ? w21 : w20);
            #pragma unroll
            for (int ntp = 0; ntp < 4; ++ntp) {
                uint32_t b00, b01, b10, b11;
                ldsm_x4(baseV + stg + (uint32_t)(ntp * 16 * KPAD + ks * 8) * 4u,
                        b00, b01, b10, b11);
                mma_tf32(o[2 * ntp],     a0, a1, a2, a3, b00, b01);
                mma_tf32(o[2 * ntp + 1], a0, a1, a2, a3, b10, b11);
            }
        }
        __syncthreads();
    }

    // Normalize + write ctx (tf32-rounded for oproj)
    const float invA = 1.0f / lA, invB = 1.0f / lB;
    const int b = bh >> 4, h = bh & 15;
    float* base0 = g_ctx + ((size_t)(b * S_) + mrow0) * DOUT + h * HD_;
    float* base1 = base0 + (size_t)8 * DOUT;
    #pragma unroll
    for (int nt = 0; nt < 8; ++nt) {
        int col = nt * 8 + 2 * q;
        float2 v0 = {rtf(o[nt][0] * invA), rtf(o[nt][1] * invA)};
        float2 v1 = {rtf(o[nt][2] * invB), rtf(o[nt][3] * invB)};
        *reinterpret_cast<float2*>(base0 + col) = v0;
        *reinterpret_cast<float2*>(base1 + col) = v1;
    }
}

// ---------------------------------------------------------------------------
extern "C" void kernel_launch(void* const* d_in, const int* in_sizes, int n_in,
                              void* d_out, int out_size)
{
    const float* x  = (const float*)d_in[0];
    const float* Wq = (const float*)d_in[1];
    const float* Wk = (const float*)d_in[2];
    const float* Wv = (const float*)d_in[3];
    const float* Wo = (const float*)d_in[4];
    const float* bo = (const float*)d_in[5];
    float* out = (float*)d_out;

    const int gemm_smem  = 4 * GSTGW * 4;   // 73728 B
    const int flash_smem = 4 * KSTGW * 4;   // 69632 B
    cudaFuncSetAttribute(qkv_tc_kernel,
        cudaFuncAttributeMaxDynamicSharedMemorySize, gemm_smem);
    cudaFuncSetAttribute(oproj_tc_kernel,
        cudaFuncAttributeMaxDynamicSharedMemorySize, gemm_smem);
    cudaFuncSetAttribute(flash_tc_kernel,
        cudaFuncAttributeMaxDynamicSharedMemorySize, flash_smem);

    const int nCvt = (XF4 + DOUT * DOUT / 4 + 255) / 256;
    cvt_pre_kernel<<<nCvt, 256>>>(x, Wo);
    transpose3_kernel<<<dim3(32, 32, 3), dim3(32, 8)>>>(Wq, Wk, Wv);
    qkv_tc_kernel<<<dim3(64, 24), 256, gemm_smem>>>();
    flash_tc_kernel<<<dim3(16, 64), 256, flash_smem>>>();
    oproj_tc_kernel<<<dim3(64, 8), 256, gemm_smem>>>(bo, out);
}

// round 7
// speedup vs baseline: 13.9073x; 1.7563x over previous
#include <cuda_runtime.h>
#include <cuda_fp16.h>
#include <cstdint>

#define B_   4
#define S_   2048
#define DIN  1024
#define DOUT 1024
#define H_   16
#define HD_  64
#define KDIM 1024

// ---------------------------------------------------------------------------
// Scratch (module-scope device arrays: allowed; no runtime allocation)
// ---------------------------------------------------------------------------
__device__ __half g_Q[B_ * H_ * S_ * HD_];   // (b,h,s,hd), pre-scaled by 0.125*log2e
__device__ __half g_K[B_ * H_ * S_ * HD_];   // (b,h,s,hd)
__device__ __half g_V[B_ * H_ * S_ * HD_];   // (b,h,s,hd)
__device__ __half g_ctx[B_ * S_ * DOUT];     // (b,s,d)
__device__ __half g_WT[3 * DIN * DOUT];      // Wq^T,Wk^T,Wv^T [n][k]
__device__ __half g_X [B_ * S_ * DIN];       // x
__device__ __half g_Wo[DOUT * DOUT];         // Wo [n][k]

// ---------------------------------------------------------------------------
// helpers
// ---------------------------------------------------------------------------
__device__ __forceinline__ uint32_t pack_h2(float lo, float hi) {
    uint32_t d;
    asm("cvt.rn.f16x2.f32 %0, %1, %2;" : "=r"(d) : "f"(hi), "f"(lo));
    return d;
}
__device__ __forceinline__ float fexp2(float x) {
    float y;
    asm("ex2.approx.f32 %0, %1;" : "=f"(y) : "f"(x));
    return y;
}
__device__ __forceinline__ uint32_t smem_u32(const void* p) {
    uint32_t a;
    asm("{ .reg .u64 t; cvta.to.shared.u64 t, %1; cvt.u32.u64 %0, t; }"
        : "=r"(a) : "l"(p));
    return a;
}
__device__ __forceinline__ void cp16(uint32_t dst, const void* src) {
    asm volatile("cp.async.cg.shared.global [%0], [%1], 16;"
                 :: "r"(dst), "l"(src) : "memory");
}
#define CP_COMMIT() asm volatile("cp.async.commit_group;" ::: "memory")
#define CP_WAIT(n)  asm volatile("cp.async.wait_group %0;" :: "n"(n) : "memory")

__device__ __forceinline__ void ldsm_x4(uint32_t addr,
    uint32_t& r0, uint32_t& r1, uint32_t& r2, uint32_t& r3)
{
    asm volatile("ldmatrix.sync.aligned.m8n8.x4.shared.b16 {%0,%1,%2,%3}, [%4];"
        : "=r"(r0), "=r"(r1), "=r"(r2), "=r"(r3) : "r"(addr));
}
__device__ __forceinline__ void ldsm_x4_t(uint32_t addr,
    uint32_t& r0, uint32_t& r1, uint32_t& r2, uint32_t& r3)
{
    asm volatile("ldmatrix.sync.aligned.m8n8.x4.trans.shared.b16 {%0,%1,%2,%3}, [%4];"
        : "=r"(r0), "=r"(r1), "=r"(r2), "=r"(r3) : "r"(addr));
}

// D += A*B, m16n8k16 f16 inputs, fp32 accumulate
__device__ __forceinline__ void mma_f16(float* d,
    uint32_t a0, uint32_t a1, uint32_t a2, uint32_t a3,
    uint32_t b0, uint32_t b1)
{
    asm volatile(
        "mma.sync.aligned.m16n8k16.row.col.f32.f16.f16.f32 "
        "{%0,%1,%2,%3}, {%4,%5,%6,%7}, {%8,%9}, {%0,%1,%2,%3};"
        : "+f"(d[0]), "+f"(d[1]), "+f"(d[2]), "+f"(d[3])
        : "r"(a0), "r"(a1), "r"(a2), "r"(a3), "r"(b0), "r"(b1));
}

// ---------------------------------------------------------------------------
// Kernel P: pre-convert x -> g_X and Wo -> g_Wo (f16)
// ---------------------------------------------------------------------------
#define XF4 (B_ * S_ * DIN / 4)
__global__ __launch_bounds__(256) void cvt_pre_kernel(
    const float* __restrict__ x, const float* __restrict__ Wo)
{
    int i = blockIdx.x * 256 + threadIdx.x;
    if (i < XF4) {
        float4 v = *reinterpret_cast<const float4*>(x + (size_t)i * 4);
        uint2 r = {pack_h2(v.x, v.y), pack_h2(v.z, v.w)};
        reinterpret_cast<uint2*>(g_X)[i] = r;
    } else {
        int j = i - XF4;
        float4 v = *reinterpret_cast<const float4*>(Wo + (size_t)j * 4);
        uint2 r = {pack_h2(v.x, v.y), pack_h2(v.z, v.w)};
        reinterpret_cast<uint2*>(g_Wo)[j] = r;
    }
}

// ---------------------------------------------------------------------------
// Kernel 0: transpose Wq/Wk/Wv ([K,N] -> [N,K]) + f16 convert, into g_WT
// ---------------------------------------------------------------------------
__global__ __launch_bounds__(256) void transpose3_kernel(
    const float* __restrict__ Wq,
    const float* __restrict__ Wk,
    const float* __restrict__ Wv)
{
    __shared__ float t[32][33];
    const float* src = (blockIdx.z == 0) ? Wq : (blockIdx.z == 1) ? Wk : Wv;
    __half* dst = g_WT + (size_t)blockIdx.z * DIN * DOUT;
    const int bx = blockIdx.x * 32, by = blockIdx.y * 32;
    const int tx = threadIdx.x, ty = threadIdx.y;
    #pragma unroll
    for (int i = 0; i < 32; i += 8)
        t[ty + i][tx] = src[(size_t)(by + ty + i) * DOUT + bx + tx];
    __syncthreads();
    #pragma unroll
    for (int i = 0; i < 32; i += 8)
        dst[(size_t)(bx + ty + i) * DIN + by + tx] = __float2half_rn(t[tx][ty + i]);
}

// ---------------------------------------------------------------------------
// GEMM f16: C[128x128] = A[128xK] * B[128xK]^T, fp32 accum.
// 256 threads, 8 warps (2m x 4n), warp tile 64x32, BK=64, double buffered.
// smem row stride 72 f16 (144B).
// ---------------------------------------------------------------------------
#define GPADH 72
#define GSTGB (128 * GPADH * 2)    // 18432 bytes / stage
#define NCH64 (KDIM / 64)

#define GEMM_ISSUE(ch, stage) do {                                           \
    _Pragma("unroll")                                                        \
    for (int i_ = 0; i_ < 4; ++i_) {                                         \
        int f_ = tid + i_ * 256, row_ = f_ >> 3, k8_ = f_ & 7;               \
        uint32_t off_ = (uint32_t)(stage) * GSTGB +                          \
                        (uint32_t)(row_ * GPADH + k8_ * 8) * 2u;             \
        cp16(uA + off_, Asrc + (size_t)row_ * KDIM + (ch) * 64 + k8_ * 8);   \
        cp16(uB + off_, Bsrc + (size_t)row_ * KDIM + (ch) * 64 + k8_ * 8);   \
    }                                                                        \
    CP_COMMIT();                                                             \
} while (0)

__device__ __forceinline__ void gemm_f16_mainloop(
    const __half* __restrict__ Asrc, const __half* __restrict__ Bsrc,
    uint32_t uA, uint32_t uB, float acc[4][4][4], int tid, int wm, int wn)
{
    const int lane = tid & 31;
    #pragma unroll
    for (int mt = 0; mt < 4; ++mt)
        #pragma unroll
        for (int nt = 0; nt < 4; ++nt)
            #pragma unroll
            for (int j = 0; j < 4; ++j) acc[mt][nt][j] = 0.0f;

    const uint32_t baseA = uA +
        (uint32_t)((wm * 64 + (lane & 15)) * GPADH + (lane >> 4) * 8) * 2u;
    const uint32_t baseB = uB +
        (uint32_t)((wn * 32 + (lane & 15)) * GPADH + (lane >> 4) * 8) * 2u;

    GEMM_ISSUE(0, 0);
    for (int ch = 0; ch < NCH64; ++ch) {
        const int cur = ch & 1;
        if (ch + 1 < NCH64) { GEMM_ISSUE(ch + 1, cur ^ 1); CP_WAIT(1); }
        else                { CP_WAIT(0); }
        __syncthreads();

        const uint32_t stg = (uint32_t)cur * GSTGB;
        #pragma unroll
        for (int ks = 0; ks < 4; ++ks) {
            uint32_t a[4][4], b[4][2];
            #pragma unroll
            for (int mt = 0; mt < 4; ++mt)
                ldsm_x4(baseA + stg + (uint32_t)(mt * 16 * GPADH + ks * 16) * 2u,
                        a[mt][0], a[mt][1], a[mt][2], a[mt][3]);
            #pragma unroll
            for (int ntp = 0; ntp < 2; ++ntp) {
                uint32_t r0, r1, r2, r3;
                ldsm_x4(baseB + stg + (uint32_t)(ntp * 16 * GPADH + ks * 16) * 2u,
                        r0, r1, r2, r3);
                b[2 * ntp][0] = r0; b[2 * ntp][1] = r2;
                b[2 * ntp + 1][0] = r1; b[2 * ntp + 1][1] = r3;
            }
            #pragma unroll
            for (int mt = 0; mt < 4; ++mt)
                #pragma unroll
                for (int nt = 0; nt < 4; ++nt)
                    mma_f16(acc[mt][nt], a[mt][0], a[mt][1], a[mt][2], a[mt][3],
                            b[nt][0], b[nt][1]);
        }
        __syncthreads();
    }
}

// ---------------------------------------------------------------------------
// Kernel 1: QKV projection.  grid (64, 24), 256 threads, dyn smem.
// Q pre-scaled by 0.125*log2(e); all outputs f16 (b,h,s,hd).
// ---------------------------------------------------------------------------
__global__ __launch_bounds__(256, 2) void qkv_tc_kernel()
{
    extern __shared__ uint32_t dyn[];
    const uint32_t uA = smem_u32(dyn);
    const uint32_t uB = uA + 2 * GSTGB;

    const int tid = threadIdx.x;
    const int wid = tid >> 5, lane = tid & 31;
    const int g = lane >> 2, q = lane & 3;
    const int wm = wid >> 2, wn = wid & 3;

    const int rowBase = blockIdx.x * 128;
    const int n0glob  = blockIdx.y * 128;
    const int w       = n0glob >> 10;
    const int nw      = n0glob & 1023;

    float acc[4][4][4];
    gemm_f16_mainloop(g_X + (size_t)rowBase * KDIM,
                      g_WT + (size_t)n0glob * KDIM,
                      uA, uB, acc, tid, wm, wn);

    __half* obuf = (w == 0) ? g_Q : (w == 1) ? g_K : g_V;
    const float scale = (w == 0) ? 0.125f * 1.4426950408889634f : 1.0f;
    #pragma unroll
    for (int mt = 0; mt < 4; ++mt) {
        int m0 = rowBase + wm * 64 + mt * 16 + g;
        int b0 = m0 >> 11, s0 = m0 & 2047;
        int m1 = m0 + 8;
        int b1 = m1 >> 11, s1 = m1 & 2047;
        #pragma unroll
        for (int nt = 0; nt < 4; ++nt) {
            int n  = nw + wn * 32 + nt * 8 + 2 * q;
            int h  = n >> 6, hd = n & 63;
            uint32_t v0 = pack_h2(acc[mt][nt][0] * scale, acc[mt][nt][1] * scale);
            uint32_t v1 = pack_h2(acc[mt][nt][2] * scale, acc[mt][nt][3] * scale);
            *reinterpret_cast<uint32_t*>(
                &obuf[(((size_t)(b0 * H_ + h) * S_) + s0) * HD_ + hd]) = v0;
            *reinterpret_cast<uint32_t*>(
                &obuf[(((size_t)(b1 * H_ + h) * S_) + s1) * HD_ + hd]) = v1;
        }
    }
}

// ---------------------------------------------------------------------------
// Kernel 3: output projection.  out = ctx @ Wo^T + bo (fp32 out).  grid (64, 8).
// ---------------------------------------------------------------------------
__global__ __launch_bounds__(256, 2) void oproj_tc_kernel(
    const float* __restrict__ bo, float* __restrict__ out)
{
    extern __shared__ uint32_t dyn[];
    const uint32_t uA = smem_u32(dyn);
    const uint32_t uB = uA + 2 * GSTGB;

    const int tid = threadIdx.x;
    const int wid = tid >> 5, lane = tid & 31;
    const int g = lane >> 2, q = lane & 3;
    const int wm = wid >> 2, wn = wid & 3;

    const int rowBase = blockIdx.x * 128;
    const int n0      = blockIdx.y * 128;

    float acc[4][4][4];
    gemm_f16_mainloop(g_ctx + (size_t)rowBase * KDIM,
                      g_Wo + (size_t)n0 * KDIM,
                      uA, uB, acc, tid, wm, wn);

    #pragma unroll
    for (int mt = 0; mt < 4; ++mt) {
        int m0 = rowBase + wm * 64 + mt * 16 + g;
        #pragma unroll
        for (int nt = 0; nt < 4; ++nt) {
            int n = n0 + wn * 32 + nt * 8 + 2 * q;
            float2 bias = *reinterpret_cast<const float2*>(&bo[n]);
            float2 v0 = {acc[mt][nt][0] + bias.x, acc[mt][nt][1] + bias.y};
            float2 v1 = {acc[mt][nt][2] + bias.x, acc[mt][nt][3] + bias.y};
            *reinterpret_cast<float2*>(&out[(size_t)m0 * DOUT + n])       = v0;
            *reinterpret_cast<float2*>(&out[(size_t)(m0 + 8) * DOUT + n]) = v1;
        }
    }
}

// ---------------------------------------------------------------------------
// Kernel 2: causal flash attention, f16 MMA (m16n8k16), cp.async double buffer.
// 128 queries per block, 8 warps x 16 rows.  grid (16, 64), 256 threads.
// S C-frag packs directly into P A-frag (FA2 identity) — zero shuffles.
// K smem [key][72] f16 (B-frags, non-trans); V smem [key][72] f16 (trans ldsm).
// ---------------------------------------------------------------------------
#define KPADH 72
#define KSTGB (64 * KPADH * 2)    // 9216 bytes per stage

#define FLASH_ISSUE(c, stage) do {                                           \
    const __half* Kp_ = g_K + ((size_t)bh * S_ + (c) * 64) * HD_;            \
    const __half* Vp_ = g_V + ((size_t)bh * S_ + (c) * 64) * HD_;            \
    _Pragma("unroll")                                                        \
    for (int i_ = 0; i_ < 2; ++i_) {                                         \
        int f_ = tid + i_ * 256, row_ = f_ >> 3, k8_ = f_ & 7;               \
        uint32_t so_ = (uint32_t)(stage) * KSTGB +                           \
                       (uint32_t)(row_ * KPADH + k8_ * 8) * 2u;              \
        cp16(uK + so_, Kp_ + row_ * HD_ + k8_ * 8);                          \
        cp16(uV + so_, Vp_ + row_ * HD_ + k8_ * 8);                          \
    }                                                                        \
    CP_COMMIT();                                                             \
} while (0)

__global__ __launch_bounds__(256, 2) void flash_tc_kernel()
{
    extern __shared__ uint32_t dyn[];
    const uint32_t uK = smem_u32(dyn);
    const uint32_t uV = uK + 2 * KSTGB;

    const int tid  = threadIdx.x;
    const int wid  = tid >> 5, lane = tid & 31;
    const int g    = lane >> 2, q = lane & 3;
    const int qt   = (int)gridDim.x - 1 - (int)blockIdx.x;  // big tiles first
    const int bh   = blockIdx.y;
    const int mrow0 = qt * 128 + wid * 16 + g;

    // ldmatrix lane addressing
    const uint32_t baseK = uK +
        (uint32_t)((lane & 15) * KPADH + (lane >> 4) * 8) * 2u;
    const uint32_t baseV = uV +
        (uint32_t)((lane & 15) * KPADH + (lane >> 4) * 8) * 2u;

    // Q A-fragments (g_Q already scaled by 0.125*log2e, f16)
    uint32_t qf[4][4];
    {
        const __half* Q0 = g_Q + ((size_t)bh * S_ + mrow0) * HD_;
        const __half* Q1 = Q0 + (size_t)8 * HD_;
        #pragma unroll
        for (int ks = 0; ks < 4; ++ks) {
            qf[ks][0] = *reinterpret_cast<const uint32_t*>(Q0 + ks * 16 + 2 * q);
            qf[ks][1] = *reinterpret_cast<const uint32_t*>(Q1 + ks * 16 + 2 * q);
            qf[ks][2] = *reinterpret_cast<const uint32_t*>(Q0 + ks * 16 + 8 + 2 * q);
            qf[ks][3] = *reinterpret_cast<const uint32_t*>(Q1 + ks * 16 + 8 + 2 * q);
        }
    }

    float o[8][4];
    #pragma unroll
    for (int nt = 0; nt < 8; ++nt)
        #pragma unroll
        for (int j = 0; j < 4; ++j) o[nt][j] = 0.0f;
    float mA = -1e30f, mB = -1e30f, lA = 0.0f, lB = 0.0f;

    const int nch = 2 * qt + 2;
    FLASH_ISSUE(0, 0);
    for (int c = 0; c < nch; ++c) {
        const int cur = c & 1;
        if (c + 1 < nch) { FLASH_ISSUE(c + 1, cur ^ 1); CP_WAIT(1); }
        else             { CP_WAIT(0); }
        __syncthreads();

        const uint32_t stg = (uint32_t)cur * KSTGB;

        // S = Q K^T  (log2 units); 8 key-tiles of n=8
        float s[8][4];
        #pragma unroll
        for (int nt = 0; nt < 8; ++nt)
            #pragma unroll
            for (int j = 0; j < 4; ++j) s[nt][j] = 0.0f;
        #pragma unroll
        for (int ks = 0; ks < 4; ++ks) {
            #pragma unroll
            for (int ntp = 0; ntp < 4; ++ntp) {
                uint32_t r0, r1, r2, r3;
                ldsm_x4(baseK + stg + (uint32_t)(ntp * 16 * KPADH + ks * 16) * 2u,
                        r0, r1, r2, r3);
                mma_f16(s[2 * ntp],     qf[ks][0], qf[ks][1], qf[ks][2], qf[ks][3], r0, r2);
                mma_f16(s[2 * ntp + 1], qf[ks][0], qf[ks][1], qf[ks][2], qf[ks][3], r1, r3);
            }
        }

        if (c >= 2 * qt) {   // causal mask, last two chunks only
            int kb = c * 64;
            #pragma unroll
            for (int nt = 0; nt < 8; ++nt) {
                int col = kb + nt * 8 + 2 * q;
                if (col     > mrow0)     s[nt][0] = -1e30f;
                if (col + 1 > mrow0)     s[nt][1] = -1e30f;
                if (col     > mrow0 + 8) s[nt][2] = -1e30f;
                if (col + 1 > mrow0 + 8) s[nt][3] = -1e30f;
            }
        }

        // online softmax
        float tmA = -1e30f, tmB = -1e30f;
        #pragma unroll
        for (int nt = 0; nt < 8; ++nt) {
            tmA = fmaxf(tmA, fmaxf(s[nt][0], s[nt][1]));
            tmB = fmaxf(tmB, fmaxf(s[nt][2], s[nt][3]));
        }
        tmA = fmaxf(tmA, __shfl_xor_sync(0xffffffffu, tmA, 1));
        tmA = fmaxf(tmA, __shfl_xor_sync(0xffffffffu, tmA, 2));
        tmB = fmaxf(tmB, __shfl_xor_sync(0xffffffffu, tmB, 1));
        tmB = fmaxf(tmB, __shfl_xor_sync(0xffffffffu, tmB, 2));
        float mnA = fmaxf(mA, tmA), mnB = fmaxf(mB, tmB);
        float corrA = fexp2(mA - mnA), corrB = fexp2(mB - mnB);
        lA *= corrA; lB *= corrB;
        #pragma unroll
        for (int nt = 0; nt < 8; ++nt) {
            o[nt][0] *= corrA; o[nt][1] *= corrA;
            o[nt][2] *= corrB; o[nt][3] *= corrB;
        }

        float sumA = 0.0f, sumB = 0.0f;
        #pragma unroll
        for (int nt = 0; nt < 8; ++nt) {
            float p0 = fexp2(s[nt][0] - mnA);
            float p1 = fexp2(s[nt][1] - mnA);
            float p2 = fexp2(s[nt][2] - mnB);
            float p3 = fexp2(s[nt][3] - mnB);
            sumA += p0 + p1; sumB += p2 + p3;
            s[nt][0] = p0; s[nt][1] = p1; s[nt][2] = p2; s[nt][3] = p3;
        }
        sumA += __shfl_xor_sync(0xffffffffu, sumA, 1);
        sumA += __shfl_xor_sync(0xffffffffu, sumA, 2);
        sumB += __shfl_xor_sync(0xffffffffu, sumB, 1);
        sumB += __shfl_xor_sync(0xffffffffu, sumB, 2);
        lA += sumA; lB += sumB;
        mA = mnA; mB = mnB;

        // pack P C-frags -> A-frags (FA2 identity, zero shuffles)
        uint32_t pa[4][4];
        #pragma unroll
        for (int kk = 0; kk < 4; ++kk) {
            pa[kk][0] = pack_h2(s[2 * kk][0],     s[2 * kk][1]);
            pa[kk][1] = pack_h2(s[2 * kk][2],     s[2 * kk][3]);
            pa[kk][2] = pack_h2(s[2 * kk + 1][0], s[2 * kk + 1][1]);
            pa[kk][3] = pack_h2(s[2 * kk + 1][2], s[2 * kk + 1][3]);
        }

        // O += P V   (V B-frags via ldmatrix.trans from [key][hd])
        #pragma unroll
        for (int ks = 0; ks < 4; ++ks) {
            #pragma unroll
            for (int hdp = 0; hdp < 4; ++hdp) {
                uint32_t r0, r1, r2, r3;
                ldsm_x4_t(baseV + stg + (uint32_t)(ks * 16 * KPADH + hdp * 16) * 2u,
                          r0, r1, r2, r3);
                mma_f16(o[2 * hdp],     pa[ks][0], pa[ks][1], pa[ks][2], pa[ks][3], r0, r1);
                mma_f16(o[2 * hdp + 1], pa[ks][0], pa[ks][1], pa[ks][2], pa[ks][3], r2, r3);
            }
        }
        __syncthreads();
    }

    // Normalize + write ctx (f16) in (b, s, h*64 + hd)
    const float invA = 1.0f / lA, invB = 1.0f / lB;
    const int b = bh >> 4, h = bh & 15;
    __half* base0 = g_ctx + ((size_t)(b * S_) + mrow0) * DOUT + h * HD_;
    __half* base1 = base0 + (size_t)8 * DOUT;
    #pragma unroll
    for (int nt = 0; nt < 8; ++nt) {
        int col = nt * 8 + 2 * q;
        *reinterpret_cast<uint32_t*>(base0 + col) =
            pack_h2(o[nt][0] * invA, o[nt][1] * invA);
        *reinterpret_cast<uint32_t*>(base1 + col) =
            pack_h2(o[nt][2] * invB, o[nt][3] * invB);
    }
}

// ---------------------------------------------------------------------------
extern "C" void kernel_launch(void* const* d_in, const int* in_sizes, int n_in,
                              void* d_out, int out_size)
{
    const float* x  = (const float*)d_in[0];
    const float* Wq = (const float*)d_in[1];
    const float* Wk = (const float*)d_in[2];
    const float* Wv = (const float*)d_in[3];
    const float* Wo = (const float*)d_in[4];
    const float* bo = (const float*)d_in[5];
    float* out = (float*)d_out;

    const int gemm_smem  = 4 * GSTGB;   // 73728 B
    const int flash_smem = 4 * KSTGB;   // 36864 B
    cudaFuncSetAttribute(qkv_tc_kernel,
        cudaFuncAttributeMaxDynamicSharedMemorySize, gemm_smem);
    cudaFuncSetAttribute(oproj_tc_kernel,
        cudaFuncAttributeMaxDynamicSharedMemorySize, gemm_smem);
    cudaFuncSetAttribute(flash_tc_kernel,
        cudaFuncAttributeMaxDynamicSharedMemorySize, flash_smem);

    const int nCvt = (XF4 + DOUT * DOUT / 4 + 255) / 256;
    cvt_pre_kernel<<<nCvt, 256>>>(x, Wo);
    transpose3_kernel<<<dim3(32, 32, 3), dim3(32, 8)>>>(Wq, Wk, Wv);
    qkv_tc_kernel<<<dim3(64, 24), 256, gemm_smem>>>();
    flash_tc_kernel<<<dim3(16, 64), 256, flash_smem>>>();
    oproj_tc_kernel<<<dim3(64, 8), 256, gemm_smem>>>(bo, out);
}